// round 1
// baseline (speedup 1.0000x reference)
#include <cuda_runtime.h>
#include <math.h>

#define BB 2
#define SS 2048
#define HH 1024
#define NH 16
#define HD 64
#define MTOT (BB*SS)   // 4096

// Scratch (device globals: allocation-free rule)
__device__ float g_q[BB*NH*SS*HD];
__device__ float g_k[BB*NH*SS*HD];
__device__ float g_v[BB*NH*SS*HD];
__device__ float g_ctx[BB*SS*HH];
__device__ float g_x[BB*SS*HH];

// ---------------------------------------------------------------------------
// GEMM: C[m][n] = sum_k A[m][k] * W[n][k]  (+bias, +epilogue)
// MODE 0: A = hidden, z in {0,1,2} selects (Wq,bq)->g_q, (Wk,bk)->g_k, (Wv,bv)->g_v
//         output written in head-major layout [B*NH, S, HD]
// MODE 1: A = g_ctx, W0/b0 = Wd/bd, out = g_x = gemm + bias + resid(hidden)
// ---------------------------------------------------------------------------
template<int MODE>
__global__ __launch_bounds__(256) void gemm_kernel(
    const float* __restrict__ A_in,
    const float* __restrict__ W0, const float* __restrict__ b0,
    const float* __restrict__ W1, const float* __restrict__ b1,
    const float* __restrict__ W2, const float* __restrict__ b2,
    const float* __restrict__ resid)
{
    __shared__ float As[16][132];
    __shared__ float Bs[16][132];

    const int t  = threadIdx.x;
    const int tx = t & 15;
    const int ty = t >> 4;
    const int m0 = blockIdx.y * 128;
    const int n0 = blockIdx.x * 128;

    const float* A;
    const float* Wt;
    const float* bias;
    if (MODE == 0) {
        A = A_in;
        int z = blockIdx.z;
        Wt   = (z == 0) ? W0 : (z == 1) ? W1 : W2;
        bias = (z == 0) ? b0 : (z == 1) ? b1 : b2;
    } else {
        A = g_ctx;
        Wt = W0; bias = b0;
    }

    float acc[8][8];
    #pragma unroll
    for (int i = 0; i < 8; i++)
        #pragma unroll
        for (int j = 0; j < 8; j++) acc[i][j] = 0.f;

    for (int kt = 0; kt < HH / 16; kt++) {
        const int k0 = kt * 16;
        // load A tile: 128 rows x 16 k (coalesced float4, scatter-transpose)
        #pragma unroll
        for (int i = 0; i < 2; i++) {
            int idx = t + i * 256;              // 0..511
            int row = idx >> 2;
            int c4  = (idx & 3) * 4;
            float4 v = *(const float4*)(A + (size_t)(m0 + row) * HH + k0 + c4);
            As[c4 + 0][row] = v.x; As[c4 + 1][row] = v.y;
            As[c4 + 2][row] = v.z; As[c4 + 3][row] = v.w;
        }
        // load W tile: 128 n-rows x 16 k
        #pragma unroll
        for (int i = 0; i < 2; i++) {
            int idx = t + i * 256;
            int row = idx >> 2;
            int c4  = (idx & 3) * 4;
            float4 v = *(const float4*)(Wt + (size_t)(n0 + row) * HH + k0 + c4);
            Bs[c4 + 0][row] = v.x; Bs[c4 + 1][row] = v.y;
            Bs[c4 + 2][row] = v.z; Bs[c4 + 3][row] = v.w;
        }
        __syncthreads();

        #pragma unroll
        for (int k = 0; k < 16; k++) {
            float a[8], b[8];
            *(float4*)(a)     = *(const float4*)(&As[k][ty * 8]);
            *(float4*)(a + 4) = *(const float4*)(&As[k][ty * 8 + 4]);
            *(float4*)(b)     = *(const float4*)(&Bs[k][tx * 8]);
            *(float4*)(b + 4) = *(const float4*)(&Bs[k][tx * 8 + 4]);
            #pragma unroll
            for (int i = 0; i < 8; i++)
                #pragma unroll
                for (int j = 0; j < 8; j++)
                    acc[i][j] += a[i] * b[j];
        }
        __syncthreads();
    }

    // epilogue
    float bb[8];
    #pragma unroll
    for (int j = 0; j < 8; j++) bb[j] = bias[n0 + tx * 8 + j];

    if (MODE == 0) {
        int z = blockIdx.z;
        float* out = (z == 0) ? g_q : (z == 1) ? g_k : g_v;
        #pragma unroll
        for (int i = 0; i < 8; i++) {
            int m  = m0 + ty * 8 + i;
            int b_ = m >> 11;           // m / S
            int s_ = m & (SS - 1);
            #pragma unroll
            for (int j4 = 0; j4 < 8; j4 += 4) {
                int n    = n0 + tx * 8 + j4;
                int head = n >> 6;
                int d    = n & 63;
                float4 r;
                r.x = acc[i][j4 + 0] + bb[j4 + 0];
                r.y = acc[i][j4 + 1] + bb[j4 + 1];
                r.z = acc[i][j4 + 2] + bb[j4 + 2];
                r.w = acc[i][j4 + 3] + bb[j4 + 3];
                *(float4*)(out + (((size_t)(b_ * NH + head) * SS + s_) * HD + d)) = r;
            }
        }
    } else {
        #pragma unroll
        for (int i = 0; i < 8; i++) {
            int m = m0 + ty * 8 + i;
            #pragma unroll
            for (int j4 = 0; j4 < 8; j4 += 4) {
                int n = n0 + tx * 8 + j4;
                float4 hv = *(const float4*)(resid + (size_t)m * HH + n);
                float4 r;
                r.x = acc[i][j4 + 0] + bb[j4 + 0] + hv.x;
                r.y = acc[i][j4 + 1] + bb[j4 + 1] + hv.y;
                r.z = acc[i][j4 + 2] + bb[j4 + 2] + hv.z;
                r.w = acc[i][j4 + 3] + bb[j4 + 3] + hv.w;
                *(float4*)(g_x + (size_t)m * HH + n) = r;
            }
        }
    }
}

// ---------------------------------------------------------------------------
// Flash attention: one thread owns one query row. Block = 128 queries.
// Grid: (S/128, B*NH). K/V tiles of 32 keys staged in smem (broadcast reads).
// ---------------------------------------------------------------------------
__global__ __launch_bounds__(128, 2) void flash_kernel()
{
    __shared__ float Ks[32 * 64];
    __shared__ float Vs[32 * 64];

    const int bh = blockIdx.y;
    const int qt = blockIdx.x;
    const int t  = threadIdx.x;

    const float* Q  = g_q + ((size_t)bh * SS + qt * 128) * HD;
    const float* Kg = g_k + (size_t)bh * SS * HD;
    const float* Vg = g_v + (size_t)bh * SS * HD;

    float q[64];
    #pragma unroll
    for (int d4 = 0; d4 < 16; d4++)
        *(float4*)&q[d4 * 4] = *(const float4*)(Q + (size_t)t * 64 + d4 * 4);

    float o[64];
    #pragma unroll
    for (int d = 0; d < 64; d++) o[d] = 0.f;
    float mx = -1e30f, l = 0.f;

    for (int kt = 0; kt < SS / 32; kt++) {
        const float4* ksrc = (const float4*)(Kg + (size_t)kt * 32 * 64);
        const float4* vsrc = (const float4*)(Vg + (size_t)kt * 32 * 64);
        #pragma unroll
        for (int i = 0; i < 4; i++) {
            int idx = t + i * 128;   // 512 float4s = 2048 floats
            ((float4*)Ks)[idx] = ksrc[idx];
            ((float4*)Vs)[idx] = vsrc[idx];
        }
        __syncthreads();

        float s[32];
        float tmax = -1e30f;
        #pragma unroll
        for (int j = 0; j < 32; j++) {
            float a0 = 0.f, a1 = 0.f, a2 = 0.f, a3 = 0.f;
            #pragma unroll
            for (int d4 = 0; d4 < 16; d4++) {
                float4 kv = ((const float4*)Ks)[j * 16 + d4];
                a0 += q[d4 * 4 + 0] * kv.x;
                a1 += q[d4 * 4 + 1] * kv.y;
                a2 += q[d4 * 4 + 2] * kv.z;
                a3 += q[d4 * 4 + 3] * kv.w;
            }
            float sv = (a0 + a1 + a2 + a3) * 0.125f;
            s[j] = sv;
            tmax = fmaxf(tmax, sv);
        }

        float mnew  = fmaxf(mx, tmax);
        float alpha = __expf(mx - mnew);
        float psum  = 0.f;
        #pragma unroll
        for (int j = 0; j < 32; j++) {
            s[j] = __expf(s[j] - mnew);
            psum += s[j];
        }
        l  = l * alpha + psum;
        mx = mnew;

        #pragma unroll
        for (int d = 0; d < 64; d++) o[d] *= alpha;

        #pragma unroll
        for (int j = 0; j < 32; j++) {
            float pj = s[j];
            #pragma unroll
            for (int d4 = 0; d4 < 16; d4++) {
                float4 v = ((const float4*)Vs)[j * 16 + d4];
                o[d4 * 4 + 0] += pj * v.x;
                o[d4 * 4 + 1] += pj * v.y;
                o[d4 * 4 + 2] += pj * v.z;
                o[d4 * 4 + 3] += pj * v.w;
            }
        }
        __syncthreads();
    }

    float inv   = 1.f / l;
    int   b_    = bh >> 4;
    int   head  = bh & 15;
    int   srow  = qt * 128 + t;
    float* dst  = g_ctx + ((size_t)(b_ * SS + srow)) * HH + head * 64;
    #pragma unroll
    for (int d4 = 0; d4 < 16; d4++) {
        float4 r;
        r.x = o[d4 * 4 + 0] * inv;
        r.y = o[d4 * 4 + 1] * inv;
        r.z = o[d4 * 4 + 2] * inv;
        r.w = o[d4 * 4 + 3] * inv;
        ((float4*)dst)[d4] = r;
    }
}

// ---------------------------------------------------------------------------
// LayerNorm over rows of g_x -> out. One block per row, 256 threads.
// ---------------------------------------------------------------------------
__global__ __launch_bounds__(256) void ln_kernel(
    const float* __restrict__ gamma, const float* __restrict__ beta,
    float* __restrict__ out)
{
    __shared__ float rsum[8];
    __shared__ float rsq[8];

    const int row = blockIdx.x;
    const int t   = threadIdx.x;
    const float* x = g_x + (size_t)row * HH;

    float4 v = ((const float4*)x)[t];
    float sum = v.x + v.y + v.z + v.w;
    float sq  = v.x * v.x + v.y * v.y + v.z * v.z + v.w * v.w;

    #pragma unroll
    for (int off = 16; off > 0; off >>= 1) {
        sum += __shfl_xor_sync(0xffffffffu, sum, off);
        sq  += __shfl_xor_sync(0xffffffffu, sq, off);
    }
    int warp = t >> 5;
    if ((t & 31) == 0) { rsum[warp] = sum; rsq[warp] = sq; }
    __syncthreads();

    float tsum = 0.f, tsq = 0.f;
    #pragma unroll
    for (int w = 0; w < 8; w++) { tsum += rsum[w]; tsq += rsq[w]; }

    const float mu   = tsum * (1.f / HH);
    const float var  = tsq * (1.f / HH) - mu * mu;
    const float rstd = rsqrtf(var + 1e-5f);

    float4 g = ((const float4*)gamma)[t];
    float4 b = ((const float4*)beta)[t];
    float4 r;
    r.x = (v.x - mu) * rstd * g.x + b.x;
    r.y = (v.y - mu) * rstd * g.y + b.y;
    r.z = (v.z - mu) * rstd * g.z + b.z;
    r.w = (v.w - mu) * rstd * g.w + b.w;
    ((float4*)(out + (size_t)row * HH))[t] = r;
}

// ---------------------------------------------------------------------------
extern "C" void kernel_launch(void* const* d_in, const int* in_sizes, int n_in,
                              void* d_out, int out_size)
{
    const float* hs    = (const float*)d_in[0];
    const float* Wq    = (const float*)d_in[1];
    const float* bq    = (const float*)d_in[2];
    const float* Wk    = (const float*)d_in[3];
    const float* bk    = (const float*)d_in[4];
    const float* Wv    = (const float*)d_in[5];
    const float* bv    = (const float*)d_in[6];
    const float* Wd    = (const float*)d_in[7];
    const float* bd    = (const float*)d_in[8];
    const float* gamma = (const float*)d_in[9];
    const float* beta  = (const float*)d_in[10];
    float* out = (float*)d_out;

    // 1) QKV projections (fused over gridDim.z)
    dim3 g1(HH / 128, MTOT / 128, 3);
    gemm_kernel<0><<<g1, 256>>>(hs, Wq, bq, Wk, bk, Wv, bv, nullptr);

    // 2) Flash attention
    dim3 g2(SS / 128, BB * NH);
    flash_kernel<<<g2, 128>>>();

    // 3) Output dense + bias + residual
    dim3 g3(HH / 128, MTOT / 128, 1);
    gemm_kernel<1><<<g3, 256>>>(nullptr, Wd, bd, nullptr, nullptr, nullptr, nullptr, hs);

    // 4) LayerNorm
    ln_kernel<<<MTOT, 256>>>(gamma, beta, out);
}

// round 3
// speedup vs baseline: 1.3466x; 1.3466x over previous
#include <cuda_runtime.h>
#include <cuda_bf16.h>
#include <math.h>
#include <stdint.h>

#define BB 2
#define SS 2048
#define HH 1024
#define NH 16
#define HD 64
#define MTOT (BB*SS)   // 4096
#define KC 64
#define NCHUNK (HH / KC)

// ---------------- scratch (device globals; allocation-free rule) -----------
__device__ float g_q[BB*NH*SS*HD];
__device__ float g_k[BB*NH*SS*HD];
__device__ float g_v[BB*NH*SS*HD];
__device__ float g_ctx[BB*SS*HH];
__device__ float g_x[BB*SS*HH];

__device__ __nv_bfloat16 g_ah[MTOT*HH];     // hidden hi
__device__ __nv_bfloat16 g_al[MTOT*HH];     // hidden lo
__device__ __nv_bfloat16 g_wh[4*HH*HH];     // Wq,Wk,Wv,Wd hi
__device__ __nv_bfloat16 g_wl[4*HH*HH];     // lo
__device__ __nv_bfloat16 g_ch[MTOT*HH];     // ctx hi
__device__ __nv_bfloat16 g_cl[MTOT*HH];     // ctx lo

// ---------------- baseline-PTX helpers (sm_80+; OK under compute_103) ------
__device__ __forceinline__ void ldm4(uint32_t* r, uint32_t addr) {
    asm volatile("ldmatrix.sync.aligned.m8n8.x4.shared.b16 {%0,%1,%2,%3}, [%4];"
        : "=r"(r[0]), "=r"(r[1]), "=r"(r[2]), "=r"(r[3]) : "r"(addr));
}

__device__ __forceinline__ void mma_bf16(float* c, const uint32_t* a,
                                         uint32_t b0, uint32_t b1) {
    asm volatile(
        "mma.sync.aligned.m16n8k16.row.col.f32.bf16.bf16.f32 "
        "{%0,%1,%2,%3}, {%4,%5,%6,%7}, {%8,%9}, {%0,%1,%2,%3};"
        : "+f"(c[0]), "+f"(c[1]), "+f"(c[2]), "+f"(c[3])
        : "r"(a[0]), "r"(a[1]), "r"(a[2]), "r"(a[3]), "r"(b0), "r"(b1));
}

__device__ __forceinline__ void cpa16(uint32_t saddr, const void* g) {
    asm volatile("cp.async.cg.shared.global [%0], [%1], 16;"
        :: "r"(saddr), "l"(g) : "memory");
}
#define CP_COMMIT() asm volatile("cp.async.commit_group;" ::: "memory")
#define CP_WAIT1()  asm volatile("cp.async.wait_group 1;" ::: "memory")

// ---------------------------------------------------------------------------
// fp32 -> bf16 hi/lo split conversion
// ---------------------------------------------------------------------------
__global__ __launch_bounds__(256) void conv_kernel(
    const float* __restrict__ src, __nv_bfloat16* __restrict__ hi,
    __nv_bfloat16* __restrict__ lo, int n4)
{
    int i = blockIdx.x * blockDim.x + threadIdx.x;
    if (i >= n4) return;
    float4 v = ((const float4*)src)[i];
    __nv_bfloat16 hx = __float2bfloat16(v.x);
    __nv_bfloat16 hy = __float2bfloat16(v.y);
    __nv_bfloat16 hz = __float2bfloat16(v.z);
    __nv_bfloat16 hw = __float2bfloat16(v.w);
    __nv_bfloat16 lx = __float2bfloat16(v.x - __bfloat162float(hx));
    __nv_bfloat16 ly = __float2bfloat16(v.y - __bfloat162float(hy));
    __nv_bfloat16 lz = __float2bfloat16(v.z - __bfloat162float(hz));
    __nv_bfloat16 lw = __float2bfloat16(v.w - __bfloat162float(hw));
    ((__nv_bfloat162*)hi)[2*i]   = __nv_bfloat162(hx, hy);
    ((__nv_bfloat162*)hi)[2*i+1] = __nv_bfloat162(hz, hw);
    ((__nv_bfloat162*)lo)[2*i]   = __nv_bfloat162(lx, ly);
    ((__nv_bfloat162*)lo)[2*i+1] = __nv_bfloat162(lz, lw);
}

// ---------------------------------------------------------------------------
// HMMA GEMM (mma.sync bf16-split, cp.async double-buffered).
// C[m][n] = sum_k A[m][k] * W[n][k]  (+bias, +epilogue)
// MODE 0: A = hidden(hi/lo), z selects W/bias -> g_q/g_k/g_v head-major
// MODE 1: A = ctx(hi/lo), W = Wd -> g_x = gemm + bias + resid
// CTA tile 128x128, 8 warps (4 m x 2 n), warp tile 32x64.
// Smem per buffer: 4 tiles (Ah,Al,Bh,Bl) of 128x64 bf16 SW128 = 64KB; x2 buf.
// ---------------------------------------------------------------------------
#define GEMM_DSM (2*65536)

template<int MODE>
__global__ __launch_bounds__(256, 1) void tc_gemm(
    const float* __restrict__ b0, const float* __restrict__ b1,
    const float* __restrict__ b2, const float* __restrict__ resid)
{
    extern __shared__ __align__(1024) char dsm[];

    const int t      = threadIdx.x;
    const int wid    = t >> 5;
    const int l      = t & 31;
    const int warp_m = wid & 3;
    const int warp_n = wid >> 2;
    const int m0     = blockIdx.y * 128;
    const int n0     = blockIdx.x * 128;
    const int z      = (MODE == 0) ? blockIdx.z : 3;

    const __nv_bfloat16* Ahi = (MODE == 0) ? g_ah : g_ch;
    const __nv_bfloat16* Alo = (MODE == 0) ? g_al : g_cl;
    const __nv_bfloat16* Bhi = g_wh + (size_t)z * HH * HH;
    const __nv_bfloat16* Blo = g_wl + (size_t)z * HH * HH;
    const float* bias = (MODE == 1) ? b0 : ((z == 0) ? b0 : (z == 1) ? b1 : b2);

    const uint32_t sbase = (uint32_t)__cvta_generic_to_shared(dsm);

    float acc[2][8][4];
    #pragma unroll
    for (int i = 0; i < 2; i++)
        #pragma unroll
        for (int j = 0; j < 8; j++)
            #pragma unroll
            for (int q = 0; q < 4; q++) acc[i][j][q] = 0.f;

    // ldmatrix per-lane row bases (row & 7 == l & 7 in all cases)
    const int rA = warp_m * 32 + (l & 7) + ((l >> 3) & 1) * 8;
    const int rB = warp_n * 64 + (l & 7) + ((l >> 4) & 1) * 8;
    const int gxA = (l >> 4);        // +16B-group for A (k high half)
    const int gxB = ((l >> 3) & 1);  // +16B-group for B
    const int lxor = (l & 7);

    // stage chunk c into buffer
    auto stage = [&](int c, uint32_t bufb) {
        #pragma unroll
        for (int i = 0; i < 16; i++) {
            int idx  = i * 256 + t;           // 0..4095
            int tile = idx >> 10;
            int w    = idx & 1023;
            int row  = w >> 3;
            int g    = w & 7;
            const __nv_bfloat16* src =
                (tile == 0) ? Ahi : (tile == 1) ? Alo : (tile == 2) ? Bhi : Blo;
            int grow = ((tile < 2) ? m0 : n0) + row;
            const void* gp = src + (size_t)grow * HH + c * KC + g * 8;
            uint32_t off = (uint32_t)(row * 128 + ((g ^ (row & 7)) * 16));
            cpa16(bufb + tile * 16384 + off, gp);
        }
    };

    stage(0, sbase);
    CP_COMMIT();

    for (int c = 0; c < NCHUNK; c++) {
        if (c + 1 < NCHUNK) stage(c + 1, sbase + ((c + 1) & 1) * 65536);
        CP_COMMIT();
        CP_WAIT1();
        __syncthreads();

        const uint32_t sb = sbase + (c & 1) * 65536;
        #pragma unroll
        for (int s = 0; s < 4; s++) {
            const int gA = 2 * s + gxA;
            const int gB = 2 * s + gxB;
            uint32_t ah[2][4], al[2][4];
            #pragma unroll
            for (int mt = 0; mt < 2; mt++) {
                int row = rA + mt * 16;
                uint32_t off = (uint32_t)(row * 128 + ((gA ^ lxor) * 16));
                ldm4(ah[mt], sb + off);
                ldm4(al[mt], sb + 16384 + off);
            }
            #pragma unroll
            for (int p = 0; p < 4; p++) {
                int row = rB + p * 16;
                uint32_t off = (uint32_t)(row * 128 + ((gB ^ lxor) * 16));
                uint32_t bh[4], bl[4];
                ldm4(bh, sb + 32768 + off);
                ldm4(bl, sb + 49152 + off);
                #pragma unroll
                for (int mt = 0; mt < 2; mt++) {
                    mma_bf16(acc[mt][2*p],   ah[mt], bh[0], bh[1]);
                    mma_bf16(acc[mt][2*p+1], ah[mt], bh[2], bh[3]);
                    mma_bf16(acc[mt][2*p],   ah[mt], bl[0], bl[1]);
                    mma_bf16(acc[mt][2*p+1], ah[mt], bl[2], bl[3]);
                    mma_bf16(acc[mt][2*p],   al[mt], bh[0], bh[1]);
                    mma_bf16(acc[mt][2*p+1], al[mt], bh[2], bh[3]);
                }
            }
        }
        __syncthreads();
    }

    // ---------------- epilogue: regs -> global ----------------
    const int lr = l >> 2;
    const int lc = (l & 3) * 2;

    float2 bv[8];
    #pragma unroll
    for (int nt = 0; nt < 8; nt++)
        bv[nt] = __ldg((const float2*)(bias + n0 + warp_n * 64 + nt * 8 + lc));

    #pragma unroll
    for (int mt = 0; mt < 2; mt++) {
        #pragma unroll
        for (int half = 0; half < 2; half++) {
            int m = m0 + warp_m * 32 + mt * 16 + lr + half * 8;
            #pragma unroll
            for (int nt = 0; nt < 8; nt++) {
                int n = n0 + warp_n * 64 + nt * 8 + lc;
                float vx = acc[mt][nt][half * 2 + 0] + bv[nt].x;
                float vy = acc[mt][nt][half * 2 + 1] + bv[nt].y;
                if (MODE == 0) {
                    float* out = (z == 0) ? g_q : (z == 1) ? g_k : g_v;
                    int b_ = m >> 11;
                    int s_ = m & (SS - 1);
                    int head = n >> 6;
                    int d = n & 63;
                    float2 r; r.x = vx; r.y = vy;
                    *(float2*)(out + (((size_t)(b_ * NH + head) * SS + s_) * HD + d)) = r;
                } else {
                    float2 hv = *(const float2*)(resid + (size_t)m * HH + n);
                    float2 r; r.x = vx + hv.x; r.y = vy + hv.y;
                    *(float2*)(g_x + (size_t)m * HH + n) = r;
                }
            }
        }
    }
}

// ---------------------------------------------------------------------------
// Flash attention: one thread owns one query row (fp32)
// ---------------------------------------------------------------------------
__global__ __launch_bounds__(128, 2) void flash_kernel()
{
    __shared__ float Ks[32 * 64];
    __shared__ float Vs[32 * 64];

    const int bh = blockIdx.y;
    const int qt = blockIdx.x;
    const int t  = threadIdx.x;

    const float* Q  = g_q + ((size_t)bh * SS + qt * 128) * HD;
    const float* Kg = g_k + (size_t)bh * SS * HD;
    const float* Vg = g_v + (size_t)bh * SS * HD;

    float q[64];
    #pragma unroll
    for (int d4 = 0; d4 < 16; d4++)
        *(float4*)&q[d4 * 4] = *(const float4*)(Q + (size_t)t * 64 + d4 * 4);

    float o[64];
    #pragma unroll
    for (int d = 0; d < 64; d++) o[d] = 0.f;
    float mx = -1e30f, l = 0.f;

    for (int kt = 0; kt < SS / 32; kt++) {
        const float4* ksrc = (const float4*)(Kg + (size_t)kt * 32 * 64);
        const float4* vsrc = (const float4*)(Vg + (size_t)kt * 32 * 64);
        #pragma unroll
        for (int i = 0; i < 4; i++) {
            int idx = t + i * 128;
            ((float4*)Ks)[idx] = ksrc[idx];
            ((float4*)Vs)[idx] = vsrc[idx];
        }
        __syncthreads();

        float s[32];
        float tmax = -1e30f;
        #pragma unroll
        for (int j = 0; j < 32; j++) {
            float a0 = 0.f, a1 = 0.f, a2 = 0.f, a3 = 0.f;
            #pragma unroll
            for (int d4 = 0; d4 < 16; d4++) {
                float4 kv = ((const float4*)Ks)[j * 16 + d4];
                a0 += q[d4 * 4 + 0] * kv.x;
                a1 += q[d4 * 4 + 1] * kv.y;
                a2 += q[d4 * 4 + 2] * kv.z;
                a3 += q[d4 * 4 + 3] * kv.w;
            }
            float sv = (a0 + a1 + a2 + a3) * 0.125f;
            s[j] = sv;
            tmax = fmaxf(tmax, sv);
        }

        float mnew  = fmaxf(mx, tmax);
        float alpha = __expf(mx - mnew);
        float psum  = 0.f;
        #pragma unroll
        for (int j = 0; j < 32; j++) {
            s[j] = __expf(s[j] - mnew);
            psum += s[j];
        }
        l  = l * alpha + psum;
        mx = mnew;

        #pragma unroll
        for (int d = 0; d < 64; d++) o[d] *= alpha;

        #pragma unroll
        for (int j = 0; j < 32; j++) {
            float pj = s[j];
            #pragma unroll
            for (int d4 = 0; d4 < 16; d4++) {
                float4 v = ((const float4*)Vs)[j * 16 + d4];
                o[d4 * 4 + 0] += pj * v.x;
                o[d4 * 4 + 1] += pj * v.y;
                o[d4 * 4 + 2] += pj * v.z;
                o[d4 * 4 + 3] += pj * v.w;
            }
        }
        __syncthreads();
    }

    float inv   = 1.f / l;
    int   b_    = bh >> 4;
    int   head  = bh & 15;
    int   srow  = qt * 128 + t;
    float* dst  = g_ctx + ((size_t)(b_ * SS + srow)) * HH + head * 64;
    #pragma unroll
    for (int d4 = 0; d4 < 16; d4++) {
        float4 r;
        r.x = o[d4 * 4 + 0] * inv;
        r.y = o[d4 * 4 + 1] * inv;
        r.z = o[d4 * 4 + 2] * inv;
        r.w = o[d4 * 4 + 3] * inv;
        ((float4*)dst)[d4] = r;
    }
}

// ---------------------------------------------------------------------------
// LayerNorm over rows of g_x -> out
// ---------------------------------------------------------------------------
__global__ __launch_bounds__(256) void ln_kernel(
    const float* __restrict__ gamma, const float* __restrict__ beta,
    float* __restrict__ out)
{
    __shared__ float rsum[8];
    __shared__ float rsq[8];

    const int row = blockIdx.x;
    const int t   = threadIdx.x;
    const float* x = g_x + (size_t)row * HH;

    float4 v = ((const float4*)x)[t];
    float sum = v.x + v.y + v.z + v.w;
    float sq  = v.x * v.x + v.y * v.y + v.z * v.z + v.w * v.w;

    #pragma unroll
    for (int off = 16; off > 0; off >>= 1) {
        sum += __shfl_xor_sync(0xffffffffu, sum, off);
        sq  += __shfl_xor_sync(0xffffffffu, sq, off);
    }
    int warp = t >> 5;
    if ((t & 31) == 0) { rsum[warp] = sum; rsq[warp] = sq; }
    __syncthreads();

    float tsum = 0.f, tsq = 0.f;
    #pragma unroll
    for (int w = 0; w < 8; w++) { tsum += rsum[w]; tsq += rsq[w]; }

    const float mu   = tsum * (1.f / HH);
    const float var  = tsq * (1.f / HH) - mu * mu;
    const float rstd = rsqrtf(var + 1e-5f);

    float4 g = ((const float4*)gamma)[t];
    float4 b = ((const float4*)beta)[t];
    float4 r;
    r.x = (v.x - mu) * rstd * g.x + b.x;
    r.y = (v.y - mu) * rstd * g.y + b.y;
    r.z = (v.z - mu) * rstd * g.z + b.z;
    r.w = (v.w - mu) * rstd * g.w + b.w;
    ((float4*)(out + (size_t)row * HH))[t] = r;
}

// ---------------------------------------------------------------------------
extern "C" void kernel_launch(void* const* d_in, const int* in_sizes, int n_in,
                              void* d_out, int out_size)
{
    const float* hs    = (const float*)d_in[0];
    const float* Wq    = (const float*)d_in[1];
    const float* bq    = (const float*)d_in[2];
    const float* Wk    = (const float*)d_in[3];
    const float* bk    = (const float*)d_in[4];
    const float* Wv    = (const float*)d_in[5];
    const float* bv    = (const float*)d_in[6];
    const float* Wd    = (const float*)d_in[7];
    const float* bd    = (const float*)d_in[8];
    const float* gamma = (const float*)d_in[9];
    const float* beta  = (const float*)d_in[10];
    float* out = (float*)d_out;

    cudaFuncSetAttribute(tc_gemm<0>, cudaFuncAttributeMaxDynamicSharedMemorySize, GEMM_DSM);
    cudaFuncSetAttribute(tc_gemm<1>, cudaFuncAttributeMaxDynamicSharedMemorySize, GEMM_DSM);

    __nv_bfloat16 *p_ah, *p_al, *p_wh, *p_wl, *p_ch, *p_cl;
    cudaGetSymbolAddress((void**)&p_ah, g_ah);
    cudaGetSymbolAddress((void**)&p_al, g_al);
    cudaGetSymbolAddress((void**)&p_wh, g_wh);
    cudaGetSymbolAddress((void**)&p_wl, g_wl);
    cudaGetSymbolAddress((void**)&p_ch, g_ch);
    cudaGetSymbolAddress((void**)&p_cl, g_cl);
    float* p_ctx;
    cudaGetSymbolAddress((void**)&p_ctx, g_ctx);

    // 0) bf16 hi/lo conversions
    conv_kernel<<<(MTOT*HH/4 + 255)/256, 256>>>(hs, p_ah, p_al, MTOT*HH/4);
    conv_kernel<<<(HH*HH/4 + 255)/256, 256>>>(Wq, p_wh + 0*HH*HH, p_wl + 0*HH*HH, HH*HH/4);
    conv_kernel<<<(HH*HH/4 + 255)/256, 256>>>(Wk, p_wh + 1*HH*HH, p_wl + 1*HH*HH, HH*HH/4);
    conv_kernel<<<(HH*HH/4 + 255)/256, 256>>>(Wv, p_wh + 2*HH*HH, p_wl + 2*HH*HH, HH*HH/4);
    conv_kernel<<<(HH*HH/4 + 255)/256, 256>>>(Wd, p_wh + 3*HH*HH, p_wl + 3*HH*HH, HH*HH/4);

    // 1) QKV projections (HMMA, fused over gridDim.z)
    dim3 g1(HH / 128, MTOT / 128, 3);
    tc_gemm<0><<<g1, 256, GEMM_DSM>>>(bq, bk, bv, nullptr);

    // 2) Flash attention (fp32)
    dim3 g2(SS / 128, BB * NH);
    flash_kernel<<<g2, 128>>>();

    // 3) ctx -> bf16 split, then output dense + bias + residual (HMMA)
    conv_kernel<<<(MTOT*HH/4 + 255)/256, 256>>>(p_ctx, p_ch, p_cl, MTOT*HH/4);
    dim3 g3(HH / 128, MTOT / 128, 1);
    tc_gemm<1><<<g3, 256, GEMM_DSM>>>(bd, nullptr, nullptr, hs);

    // 4) LayerNorm
    ln_kernel<<<MTOT, 256>>>(gamma, beta, out);
}

// round 4
// speedup vs baseline: 3.3760x; 2.5070x over previous
#include <cuda_runtime.h>
#include <cuda_bf16.h>
#include <math.h>
#include <stdint.h>

#define BB 2
#define SS 2048
#define HH 1024
#define NH 16
#define HD 64
#define MTOT (BB*SS)   // 4096
#define KC 64
#define NCHUNK (HH / KC)

// ---------------- scratch (device globals; allocation-free rule) -----------
__device__ float g_x[BB*SS*HH];

__device__ __nv_bfloat16 g_ah[MTOT*HH];     // hidden hi
__device__ __nv_bfloat16 g_al[MTOT*HH];     // hidden lo
__device__ __nv_bfloat16 g_wh[4*HH*HH];     // Wq,Wk,Wv,Wd hi
__device__ __nv_bfloat16 g_wl[4*HH*HH];     // lo
__device__ __nv_bfloat16 g_ch[MTOT*HH];     // ctx hi
__device__ __nv_bfloat16 g_cl[MTOT*HH];     // ctx lo

// attention operands (bf16 hi/lo). q,k: [B*NH][S][HD]; v: transposed [B*NH][HD][S]
__device__ __nv_bfloat16 g_qh[BB*NH*SS*HD];
__device__ __nv_bfloat16 g_ql[BB*NH*SS*HD];
__device__ __nv_bfloat16 g_kh[BB*NH*SS*HD];
__device__ __nv_bfloat16 g_kl[BB*NH*SS*HD];
__device__ __nv_bfloat16 g_vth[BB*NH*HD*SS];
__device__ __nv_bfloat16 g_vtl[BB*NH*HD*SS];

// ---------------- baseline-PTX helpers (sm_80+; OK under compute_103) ------
__device__ __forceinline__ void ldm4(uint32_t* r, uint32_t addr) {
    asm volatile("ldmatrix.sync.aligned.m8n8.x4.shared.b16 {%0,%1,%2,%3}, [%4];"
        : "=r"(r[0]), "=r"(r[1]), "=r"(r[2]), "=r"(r[3]) : "r"(addr));
}

__device__ __forceinline__ void mma_bf16(float* c, const uint32_t* a,
                                         uint32_t b0, uint32_t b1) {
    asm volatile(
        "mma.sync.aligned.m16n8k16.row.col.f32.bf16.bf16.f32 "
        "{%0,%1,%2,%3}, {%4,%5,%6,%7}, {%8,%9}, {%0,%1,%2,%3};"
        : "+f"(c[0]), "+f"(c[1]), "+f"(c[2]), "+f"(c[3])
        : "r"(a[0]), "r"(a[1]), "r"(a[2]), "r"(a[3]), "r"(b0), "r"(b1));
}

__device__ __forceinline__ void cpa16(uint32_t saddr, const void* g) {
    asm volatile("cp.async.cg.shared.global [%0], [%1], 16;"
        :: "r"(saddr), "l"(g) : "memory");
}
#define CP_COMMIT() asm volatile("cp.async.commit_group;" ::: "memory")
#define CP_WAIT1()  asm volatile("cp.async.wait_group 1;" ::: "memory")

__device__ __forceinline__ uint32_t packbf(float x, float y) {
    __nv_bfloat162 h = __floats2bfloat162_rn(x, y);
    return *(uint32_t*)&h;
}

// ---------------------------------------------------------------------------
// fp32 -> bf16 hi/lo split conversion
// ---------------------------------------------------------------------------
__global__ __launch_bounds__(256) void conv_kernel(
    const float* __restrict__ src, __nv_bfloat16* __restrict__ hi,
    __nv_bfloat16* __restrict__ lo, int n4)
{
    int i = blockIdx.x * blockDim.x + threadIdx.x;
    if (i >= n4) return;
    float4 v = ((const float4*)src)[i];
    __nv_bfloat16 hx = __float2bfloat16(v.x);
    __nv_bfloat16 hy = __float2bfloat16(v.y);
    __nv_bfloat16 hz = __float2bfloat16(v.z);
    __nv_bfloat16 hw = __float2bfloat16(v.w);
    __nv_bfloat16 lx = __float2bfloat16(v.x - __bfloat162float(hx));
    __nv_bfloat16 ly = __float2bfloat16(v.y - __bfloat162float(hy));
    __nv_bfloat16 lz = __float2bfloat16(v.z - __bfloat162float(hz));
    __nv_bfloat16 lw = __float2bfloat16(v.w - __bfloat162float(hw));
    ((__nv_bfloat162*)hi)[2*i]   = __nv_bfloat162(hx, hy);
    ((__nv_bfloat162*)hi)[2*i+1] = __nv_bfloat162(hz, hw);
    ((__nv_bfloat162*)lo)[2*i]   = __nv_bfloat162(lx, ly);
    ((__nv_bfloat162*)lo)[2*i+1] = __nv_bfloat162(lz, lw);
}

// ---------------------------------------------------------------------------
// HMMA GEMM (mma.sync bf16-split, cp.async double-buffered).
// MODE 0: A = hidden(hi/lo), z selects W/bias -> q/k (bf16 split, head-major)
//         or v (bf16 split, TRANSPOSED per head). Q pre-scaled by 0.125.
// MODE 1: A = ctx(hi/lo), W = Wd -> g_x = gemm + bias + resid (fp32)
// ---------------------------------------------------------------------------
#define GEMM_DSM (2*65536)

template<int MODE>
__global__ __launch_bounds__(256, 1) void tc_gemm(
    const float* __restrict__ b0, const float* __restrict__ b1,
    const float* __restrict__ b2, const float* __restrict__ resid)
{
    extern __shared__ __align__(1024) char dsm[];

    const int t      = threadIdx.x;
    const int wid    = t >> 5;
    const int l      = t & 31;
    const int warp_m = wid & 3;
    const int warp_n = wid >> 2;
    const int m0     = blockIdx.y * 128;
    const int n0     = blockIdx.x * 128;
    const int z      = (MODE == 0) ? blockIdx.z : 3;

    const __nv_bfloat16* Ahi = (MODE == 0) ? g_ah : g_ch;
    const __nv_bfloat16* Alo = (MODE == 0) ? g_al : g_cl;
    const __nv_bfloat16* Bhi = g_wh + (size_t)z * HH * HH;
    const __nv_bfloat16* Blo = g_wl + (size_t)z * HH * HH;
    const float* bias = (MODE == 1) ? b0 : ((z == 0) ? b0 : (z == 1) ? b1 : b2);

    const uint32_t sbase = (uint32_t)__cvta_generic_to_shared(dsm);

    float acc[2][8][4];
    #pragma unroll
    for (int i = 0; i < 2; i++)
        #pragma unroll
        for (int j = 0; j < 8; j++)
            #pragma unroll
            for (int q = 0; q < 4; q++) acc[i][j][q] = 0.f;

    const int rA = warp_m * 32 + (l & 7) + ((l >> 3) & 1) * 8;
    const int rB = warp_n * 64 + (l & 7) + ((l >> 4) & 1) * 8;
    const int gxA = (l >> 4);
    const int gxB = ((l >> 3) & 1);
    const int lxor = (l & 7);

    auto stage = [&](int c, uint32_t bufb) {
        #pragma unroll
        for (int i = 0; i < 16; i++) {
            int idx  = i * 256 + t;
            int tile = idx >> 10;
            int w    = idx & 1023;
            int row  = w >> 3;
            int g    = w & 7;
            const __nv_bfloat16* src =
                (tile == 0) ? Ahi : (tile == 1) ? Alo : (tile == 2) ? Bhi : Blo;
            int grow = ((tile < 2) ? m0 : n0) + row;
            const void* gp = src + (size_t)grow * HH + c * KC + g * 8;
            uint32_t off = (uint32_t)(row * 128 + ((g ^ (row & 7)) * 16));
            cpa16(bufb + tile * 16384 + off, gp);
        }
    };

    stage(0, sbase);
    CP_COMMIT();

    for (int c = 0; c < NCHUNK; c++) {
        if (c + 1 < NCHUNK) stage(c + 1, sbase + ((c + 1) & 1) * 65536);
        CP_COMMIT();
        CP_WAIT1();
        __syncthreads();

        const uint32_t sb = sbase + (c & 1) * 65536;
        #pragma unroll
        for (int s = 0; s < 4; s++) {
            const int gA = 2 * s + gxA;
            const int gB = 2 * s + gxB;
            uint32_t ah[2][4], al[2][4];
            #pragma unroll
            for (int mt = 0; mt < 2; mt++) {
                int row = rA + mt * 16;
                uint32_t off = (uint32_t)(row * 128 + ((gA ^ lxor) * 16));
                ldm4(ah[mt], sb + off);
                ldm4(al[mt], sb + 16384 + off);
            }
            #pragma unroll
            for (int p = 0; p < 4; p++) {
                int row = rB + p * 16;
                uint32_t off = (uint32_t)(row * 128 + ((gB ^ lxor) * 16));
                uint32_t bh[4], bl[4];
                ldm4(bh, sb + 32768 + off);
                ldm4(bl, sb + 49152 + off);
                #pragma unroll
                for (int mt = 0; mt < 2; mt++) {
                    mma_bf16(acc[mt][2*p],   ah[mt], bh[0], bh[1]);
                    mma_bf16(acc[mt][2*p+1], ah[mt], bh[2], bh[3]);
                    mma_bf16(acc[mt][2*p],   ah[mt], bl[0], bl[1]);
                    mma_bf16(acc[mt][2*p+1], ah[mt], bl[2], bl[3]);
                    mma_bf16(acc[mt][2*p],   al[mt], bh[0], bh[1]);
                    mma_bf16(acc[mt][2*p+1], al[mt], bh[2], bh[3]);
                }
            }
        }
        __syncthreads();
    }

    // ---------------- epilogue ----------------
    const int lr = l >> 2;
    const int lc = (l & 3) * 2;

    float2 bv[8];
    #pragma unroll
    for (int nt = 0; nt < 8; nt++)
        bv[nt] = __ldg((const float2*)(bias + n0 + warp_n * 64 + nt * 8 + lc));

    #pragma unroll
    for (int mt = 0; mt < 2; mt++) {
        #pragma unroll
        for (int half = 0; half < 2; half++) {
            int m = m0 + warp_m * 32 + mt * 16 + lr + half * 8;
            #pragma unroll
            for (int nt = 0; nt < 8; nt++) {
                int n = n0 + warp_n * 64 + nt * 8 + lc;
                float vx = acc[mt][nt][half * 2 + 0] + bv[nt].x;
                float vy = acc[mt][nt][half * 2 + 1] + bv[nt].y;
                if (MODE == 0) {
                    int b_ = m >> 11;
                    int s_ = m & (SS - 1);
                    int head = n >> 6;
                    int d = n & 63;
                    int bh = b_ * NH + head;
                    if (z == 0) { vx *= 0.125f; vy *= 0.125f; }
                    __nv_bfloat16 hx = __float2bfloat16(vx);
                    __nv_bfloat16 hy = __float2bfloat16(vy);
                    __nv_bfloat16 ox = __float2bfloat16(vx - __bfloat162float(hx));
                    __nv_bfloat16 oy = __float2bfloat16(vy - __bfloat162float(hy));
                    if (z == 2) {
                        size_t base = ((size_t)bh * HD + d) * SS + s_;
                        g_vth[base] = hx;       g_vtl[base] = ox;
                        g_vth[base + SS] = hy;  g_vtl[base + SS] = oy;
                    } else {
                        size_t idx = ((size_t)bh * SS + s_) * HD + d;
                        __nv_bfloat16* ph = (z == 0) ? g_qh : g_kh;
                        __nv_bfloat16* pl = (z == 0) ? g_ql : g_kl;
                        *(__nv_bfloat162*)(ph + idx) = __nv_bfloat162(hx, hy);
                        *(__nv_bfloat162*)(pl + idx) = __nv_bfloat162(ox, oy);
                    }
                } else {
                    float2 hv = *(const float2*)(resid + (size_t)m * HH + n);
                    float2 r; r.x = vx + hv.x; r.y = vy + hv.y;
                    *(float2*)(g_x + (size_t)m * HH + n) = r;
                }
            }
        }
    }
}

// ---------------------------------------------------------------------------
// Flash attention on HMMA (bf16-split both GEMMs).
// Block: 128 q-rows, 8 warps (16 q-rows each). K-tile 64 keys.
// smem: buf0/buf1 (Kh,Kl,Vth,Vtl @ 8KB each = 32KB/buf), Q (hi/lo 16KB each).
// ---------------------------------------------------------------------------
#define FL_DSM 98304

__global__ __launch_bounds__(256, 1) void flash_tc()
{
    extern __shared__ __align__(1024) char dsm[];
    const int t  = threadIdx.x;
    const int w  = t >> 5;
    const int l  = t & 31;
    const int qt = blockIdx.x;
    const int bh = blockIdx.y;

    const uint32_t sbase = (uint32_t)__cvta_generic_to_shared(dsm);
    const uint32_t qbase = sbase + 65536;

    const size_t kvb = (size_t)bh * SS * HD;
    const size_t vtb = (size_t)bh * HD * SS;

    // ---- stage Q (hi/lo), group 0 ----
    #pragma unroll
    for (int i = 0; i < 8; i++) {
        int idx  = i * 256 + t;           // 0..2047
        int tile = idx >> 10;             // 0 hi, 1 lo
        int w2   = idx & 1023;
        int row  = w2 >> 3;               // 0..127
        int g    = w2 & 7;
        const __nv_bfloat16* src = tile ? g_ql : g_qh;
        const void* gp = src + kvb + (size_t)(qt * 128 + row) * HD + g * 8;
        uint32_t off = (uint32_t)(row * 128 + ((g ^ (row & 7)) * 16));
        cpa16(qbase + tile * 16384 + off, gp);
    }
    CP_COMMIT();

    auto stage_kv = [&](int kt, uint32_t bufb) {
        #pragma unroll
        for (int i = 0; i < 8; i++) {
            int idx  = i * 256 + t;       // 0..2047
            int tile = idx >> 9;          // 0 Kh,1 Kl,2 Vth,3 Vtl
            int w2   = idx & 511;
            int row  = w2 >> 3;           // 0..63
            int g    = w2 & 7;
            const void* gp;
            if (tile == 0)      gp = g_kh  + kvb + (size_t)(kt * 64 + row) * HD + g * 8;
            else if (tile == 1) gp = g_kl  + kvb + (size_t)(kt * 64 + row) * HD + g * 8;
            else if (tile == 2) gp = g_vth + vtb + (size_t)row * SS + kt * 64 + g * 8;
            else                gp = g_vtl + vtb + (size_t)row * SS + kt * 64 + g * 8;
            uint32_t off = (uint32_t)(row * 128 + ((g ^ (row & 7)) * 16));
            cpa16(bufb + tile * 8192 + off, gp);
        }
    };

    stage_kv(0, sbase);
    CP_COMMIT();
    CP_WAIT1();            // Q group done
    __syncthreads();

    // ---- Q fragments (register-resident) ----
    uint32_t qh[4][4], ql[4][4];
    {
        int row = w * 16 + (l & 7) + ((l >> 3) & 1) * 8;
        #pragma unroll
        for (int kk = 0; kk < 4; kk++) {
            uint32_t off = (uint32_t)(row * 128 + (((2 * kk + (l >> 4)) ^ (l & 7)) * 16));
            ldm4(qh[kk], qbase + off);
            ldm4(ql[kk], qbase + 16384 + off);
        }
    }

    const int rB  = (l & 7) + ((l >> 4) & 1) * 8;
    const int gxB = (l >> 3) & 1;
    const int lx  = l & 7;

    float occ[8][4];
    #pragma unroll
    for (int i = 0; i < 8; i++)
        #pragma unroll
        for (int j = 0; j < 4; j++) occ[i][j] = 0.f;
    float mx0 = -1e30f, mx1 = -1e30f, l0 = 0.f, l1 = 0.f;

    for (int kt = 0; kt < SS / 64; kt++) {
        if (kt + 1 < SS / 64) stage_kv(kt + 1, sbase + ((kt + 1) & 1) * 32768);
        CP_COMMIT();
        CP_WAIT1();
        __syncthreads();

        const uint32_t sb = sbase + (kt & 1) * 32768;

        // ---- scores S = Q K^T (bf16-split x3) ----
        float sc[8][4];
        #pragma unroll
        for (int i = 0; i < 8; i++)
            #pragma unroll
            for (int j = 0; j < 4; j++) sc[i][j] = 0.f;

        #pragma unroll
        for (int pn = 0; pn < 4; pn++) {
            int row = rB + pn * 16;
            #pragma unroll
            for (int s = 0; s < 4; s++) {
                uint32_t off = (uint32_t)(row * 128 + (((2 * s + gxB) ^ lx) * 16));
                uint32_t kh[4], kl[4];
                ldm4(kh, sb + off);
                ldm4(kl, sb + 8192 + off);
                mma_bf16(sc[2*pn],   qh[s], kh[0], kh[1]);
                mma_bf16(sc[2*pn+1], qh[s], kh[2], kh[3]);
                mma_bf16(sc[2*pn],   qh[s], kl[0], kl[1]);
                mma_bf16(sc[2*pn+1], qh[s], kl[2], kl[3]);
                mma_bf16(sc[2*pn],   ql[s], kh[0], kh[1]);
                mma_bf16(sc[2*pn+1], ql[s], kh[2], kh[3]);
            }
        }

        // ---- online softmax (rows r and r+8 per thread) ----
        float tm0 = -1e30f, tm1 = -1e30f;
        #pragma unroll
        for (int n = 0; n < 8; n++) {
            tm0 = fmaxf(tm0, fmaxf(sc[n][0], sc[n][1]));
            tm1 = fmaxf(tm1, fmaxf(sc[n][2], sc[n][3]));
        }
        tm0 = fmaxf(tm0, __shfl_xor_sync(0xffffffffu, tm0, 1));
        tm0 = fmaxf(tm0, __shfl_xor_sync(0xffffffffu, tm0, 2));
        tm1 = fmaxf(tm1, __shfl_xor_sync(0xffffffffu, tm1, 1));
        tm1 = fmaxf(tm1, __shfl_xor_sync(0xffffffffu, tm1, 2));

        float mn0 = fmaxf(mx0, tm0);
        float mn1 = fmaxf(mx1, tm1);
        float a0 = __expf(mx0 - mn0);
        float a1 = __expf(mx1 - mn1);
        mx0 = mn0; mx1 = mn1;

        float rs0 = 0.f, rs1 = 0.f;
        #pragma unroll
        for (int n = 0; n < 8; n++) {
            sc[n][0] = __expf(sc[n][0] - mn0); rs0 += sc[n][0];
            sc[n][1] = __expf(sc[n][1] - mn0); rs0 += sc[n][1];
            sc[n][2] = __expf(sc[n][2] - mn1); rs1 += sc[n][2];
            sc[n][3] = __expf(sc[n][3] - mn1); rs1 += sc[n][3];
        }
        rs0 += __shfl_xor_sync(0xffffffffu, rs0, 1);
        rs0 += __shfl_xor_sync(0xffffffffu, rs0, 2);
        rs1 += __shfl_xor_sync(0xffffffffu, rs1, 1);
        rs1 += __shfl_xor_sync(0xffffffffu, rs1, 2);
        l0 = l0 * a0 + rs0;
        l1 = l1 * a1 + rs1;

        #pragma unroll
        for (int nh = 0; nh < 8; nh++) {
            occ[nh][0] *= a0; occ[nh][1] *= a0;
            occ[nh][2] *= a1; occ[nh][3] *= a1;
        }

        // ---- pack P into A-fragments (hi/lo) ----
        uint32_t pah[4][4], pal[4][4];
        #pragma unroll
        for (int tt = 0; tt < 4; tt++) {
            #pragma unroll
            for (int jj = 0; jj < 2; jj++) {
                const float* sp = sc[2 * tt + jj];
                __nv_bfloat16 h0 = __float2bfloat16(sp[0]);
                __nv_bfloat16 h1 = __float2bfloat16(sp[1]);
                __nv_bfloat16 h2 = __float2bfloat16(sp[2]);
                __nv_bfloat16 h3 = __float2bfloat16(sp[3]);
                pah[tt][2*jj]   = packbf(__bfloat162float(h0), __bfloat162float(h1));
                pah[tt][2*jj+1] = packbf(__bfloat162float(h2), __bfloat162float(h3));
                pal[tt][2*jj]   = packbf(sp[0] - __bfloat162float(h0),
                                         sp[1] - __bfloat162float(h1));
                pal[tt][2*jj+1] = packbf(sp[2] - __bfloat162float(h2),
                                         sp[3] - __bfloat162float(h3));
            }
        }
        // fix packing: pah[tt][k] built from bf16 of sp — repack exactly:
        #pragma unroll
        for (int tt = 0; tt < 4; tt++) {
            #pragma unroll
            for (int jj = 0; jj < 2; jj++) {
                const float* sp = sc[2 * tt + jj];
                pah[tt][2*jj]   = packbf(sp[0], sp[1]);
                pah[tt][2*jj+1] = packbf(sp[2], sp[3]);
            }
        }

        // ---- ctx += P V (bf16-split x3) ----
        #pragma unroll
        for (int pd = 0; pd < 4; pd++) {
            int row = rB + pd * 16;
            #pragma unroll
            for (int tt = 0; tt < 4; tt++) {
                uint32_t off = (uint32_t)(row * 128 + (((2 * tt + gxB) ^ lx) * 16));
                uint32_t vh[4], vl[4];
                ldm4(vh, sb + 16384 + off);
                ldm4(vl, sb + 24576 + off);
                mma_bf16(occ[2*pd],   pah[tt], vh[0], vh[1]);
                mma_bf16(occ[2*pd+1], pah[tt], vh[2], vh[3]);
                mma_bf16(occ[2*pd],   pal[tt], vh[0], vh[1]);
                mma_bf16(occ[2*pd+1], pal[tt], vh[2], vh[3]);
                mma_bf16(occ[2*pd],   pah[tt], vl[0], vl[1]);
                mma_bf16(occ[2*pd+1], pah[tt], vl[2], vl[3]);
            }
        }
        __syncthreads();
    }

    // ---- epilogue: normalize, split, write ctx hi/lo ----
    const float inv0 = 1.f / l0;
    const float inv1 = 1.f / l1;
    const int b_   = bh >> 4;
    const int head = bh & 15;
    const int r    = l >> 2;
    const int c    = 2 * (l & 3);
    const int s0   = qt * 128 + w * 16 + r;
    const int s1   = s0 + 8;

    #pragma unroll
    for (int nh = 0; nh < 8; nh++) {
        int col = head * 64 + nh * 8 + c;
        {
            float v0 = occ[nh][0] * inv0;
            float v1 = occ[nh][1] * inv0;
            __nv_bfloat16 h0 = __float2bfloat16(v0);
            __nv_bfloat16 h1 = __float2bfloat16(v1);
            size_t idx = (size_t)(b_ * SS + s0) * HH + col;
            *(__nv_bfloat162*)(g_ch + idx) = __nv_bfloat162(h0, h1);
            *(__nv_bfloat162*)(g_cl + idx) = __nv_bfloat162(
                __float2bfloat16(v0 - __bfloat162float(h0)),
                __float2bfloat16(v1 - __bfloat162float(h1)));
        }
        {
            float v2 = occ[nh][2] * inv1;
            float v3 = occ[nh][3] * inv1;
            __nv_bfloat16 h2 = __float2bfloat16(v2);
            __nv_bfloat16 h3 = __float2bfloat16(v3);
            size_t idx = (size_t)(b_ * SS + s1) * HH + col;
            *(__nv_bfloat162*)(g_ch + idx) = __nv_bfloat162(h2, h3);
            *(__nv_bfloat162*)(g_cl + idx) = __nv_bfloat162(
                __float2bfloat16(v2 - __bfloat162float(h2)),
                __float2bfloat16(v3 - __bfloat162float(h3)));
        }
    }
}

// ---------------------------------------------------------------------------
// LayerNorm over rows of g_x -> out
// ---------------------------------------------------------------------------
__global__ __launch_bounds__(256) void ln_kernel(
    const float* __restrict__ gamma, const float* __restrict__ beta,
    float* __restrict__ out)
{
    __shared__ float rsum[8];
    __shared__ float rsq[8];

    const int row = blockIdx.x;
    const int t   = threadIdx.x;
    const float* x = g_x + (size_t)row * HH;

    float4 v = ((const float4*)x)[t];
    float sum = v.x + v.y + v.z + v.w;
    float sq  = v.x * v.x + v.y * v.y + v.z * v.z + v.w * v.w;

    #pragma unroll
    for (int off = 16; off > 0; off >>= 1) {
        sum += __shfl_xor_sync(0xffffffffu, sum, off);
        sq  += __shfl_xor_sync(0xffffffffu, sq, off);
    }
    int warp = t >> 5;
    if ((t & 31) == 0) { rsum[warp] = sum; rsq[warp] = sq; }
    __syncthreads();

    float tsum = 0.f, tsq = 0.f;
    #pragma unroll
    for (int w = 0; w < 8; w++) { tsum += rsum[w]; tsq += rsq[w]; }

    const float mu   = tsum * (1.f / HH);
    const float var  = tsq * (1.f / HH) - mu * mu;
    const float rstd = rsqrtf(var + 1e-5f);

    float4 g = ((const float4*)gamma)[t];
    float4 b = ((const float4*)beta)[t];
    float4 r;
    r.x = (v.x - mu) * rstd * g.x + b.x;
    r.y = (v.y - mu) * rstd * g.y + b.y;
    r.z = (v.z - mu) * rstd * g.z + b.z;
    r.w = (v.w - mu) * rstd * g.w + b.w;
    ((float4*)(out + (size_t)row * HH))[t] = r;
}

// ---------------------------------------------------------------------------
extern "C" void kernel_launch(void* const* d_in, const int* in_sizes, int n_in,
                              void* d_out, int out_size)
{
    const float* hs    = (const float*)d_in[0];
    const float* Wq    = (const float*)d_in[1];
    const float* bq    = (const float*)d_in[2];
    const float* Wk    = (const float*)d_in[3];
    const float* bk    = (const float*)d_in[4];
    const float* Wv    = (const float*)d_in[5];
    const float* bv    = (const float*)d_in[6];
    const float* Wd    = (const float*)d_in[7];
    const float* bd    = (const float*)d_in[8];
    const float* gamma = (const float*)d_in[9];
    const float* beta  = (const float*)d_in[10];
    float* out = (float*)d_out;

    cudaFuncSetAttribute(tc_gemm<0>, cudaFuncAttributeMaxDynamicSharedMemorySize, GEMM_DSM);
    cudaFuncSetAttribute(tc_gemm<1>, cudaFuncAttributeMaxDynamicSharedMemorySize, GEMM_DSM);
    cudaFuncSetAttribute(flash_tc,  cudaFuncAttributeMaxDynamicSharedMemorySize, FL_DSM);

    __nv_bfloat16 *p_ah, *p_al, *p_wh, *p_wl;
    cudaGetSymbolAddress((void**)&p_ah, g_ah);
    cudaGetSymbolAddress((void**)&p_al, g_al);
    cudaGetSymbolAddress((void**)&p_wh, g_wh);
    cudaGetSymbolAddress((void**)&p_wl, g_wl);

    // 0) bf16 hi/lo conversions (hidden + 4 weights)
    conv_kernel<<<(MTOT*HH/4 + 255)/256, 256>>>(hs, p_ah, p_al, MTOT*HH/4);
    conv_kernel<<<(HH*HH/4 + 255)/256, 256>>>(Wq, p_wh + 0*HH*HH, p_wl + 0*HH*HH, HH*HH/4);
    conv_kernel<<<(HH*HH/4 + 255)/256, 256>>>(Wk, p_wh + 1*HH*HH, p_wl + 1*HH*HH, HH*HH/4);
    conv_kernel<<<(HH*HH/4 + 255)/256, 256>>>(Wv, p_wh + 2*HH*HH, p_wl + 2*HH*HH, HH*HH/4);
    conv_kernel<<<(HH*HH/4 + 255)/256, 256>>>(Wd, p_wh + 3*HH*HH, p_wl + 3*HH*HH, HH*HH/4);

    // 1) QKV projections (HMMA) -> bf16 split q/k/vT
    dim3 g1(HH / 128, MTOT / 128, 3);
    tc_gemm<0><<<g1, 256, GEMM_DSM>>>(bq, bk, bv, nullptr);

    // 2) Flash attention (HMMA) -> ctx bf16 split
    dim3 g2(SS / 128, BB * NH);
    flash_tc<<<g2, 256, FL_DSM>>>();

    // 3) Output dense + bias + residual (HMMA)
    dim3 g3(HH / 128, MTOT / 128, 1);
    tc_gemm<1><<<g3, 256, GEMM_DSM>>>(bd, nullptr, nullptr, hs);

    // 4) LayerNorm
    ln_kernel<<<MTOT, 256>>>(gamma, beta, out);
}

// round 5
// speedup vs baseline: 3.4792x; 1.0306x over previous
#include <cuda_runtime.h>
#include <cuda_bf16.h>
#include <math.h>
#include <stdint.h>

#define BB 2
#define SS 2048
#define HH 1024
#define NH 16
#define HD 64
#define MTOT (BB*SS)   // 4096
#define KC 64
#define NCHUNK (HH / KC)

// ---------------- scratch (device globals; allocation-free rule) -----------
__device__ float g_x[BB*SS*HH];

__device__ __nv_bfloat16 g_ah[MTOT*HH];     // hidden hi
__device__ __nv_bfloat16 g_al[MTOT*HH];     // hidden lo
__device__ __nv_bfloat16 g_wh[4*HH*HH];     // Wq,Wk,Wv,Wd hi
__device__ __nv_bfloat16 g_wl[4*HH*HH];     // lo
__device__ __nv_bfloat16 g_ch[MTOT*HH];     // ctx hi
__device__ __nv_bfloat16 g_cl[MTOT*HH];     // ctx lo

// attention operands (bf16 hi/lo). q,k: [B*NH][S][HD]; v: transposed [B*NH][HD][S]
__device__ __nv_bfloat16 g_qh[BB*NH*SS*HD];
__device__ __nv_bfloat16 g_ql[BB*NH*SS*HD];
__device__ __nv_bfloat16 g_kh[BB*NH*SS*HD];
__device__ __nv_bfloat16 g_kl[BB*NH*SS*HD];
__device__ __nv_bfloat16 g_vth[BB*NH*HD*SS];
__device__ __nv_bfloat16 g_vtl[BB*NH*HD*SS];

// ---------------- baseline-PTX helpers (sm_80+; OK under compute_103) ------
__device__ __forceinline__ void ldm4(uint32_t* r, uint32_t addr) {
    asm volatile("ldmatrix.sync.aligned.m8n8.x4.shared.b16 {%0,%1,%2,%3}, [%4];"
        : "=r"(r[0]), "=r"(r[1]), "=r"(r[2]), "=r"(r[3]) : "r"(addr));
}

__device__ __forceinline__ void mma_bf16(float* c, const uint32_t* a,
                                         uint32_t b0, uint32_t b1) {
    asm volatile(
        "mma.sync.aligned.m16n8k16.row.col.f32.bf16.bf16.f32 "
        "{%0,%1,%2,%3}, {%4,%5,%6,%7}, {%8,%9}, {%0,%1,%2,%3};"
        : "+f"(c[0]), "+f"(c[1]), "+f"(c[2]), "+f"(c[3])
        : "r"(a[0]), "r"(a[1]), "r"(a[2]), "r"(a[3]), "r"(b0), "r"(b1));
}

__device__ __forceinline__ void cpa16(uint32_t saddr, const void* g) {
    asm volatile("cp.async.cg.shared.global [%0], [%1], 16;"
        :: "r"(saddr), "l"(g) : "memory");
}
#define CP_COMMIT() asm volatile("cp.async.commit_group;" ::: "memory")
#define CP_WAIT1()  asm volatile("cp.async.wait_group 1;" ::: "memory")

__device__ __forceinline__ uint32_t packbf(float x, float y) {
    __nv_bfloat162 h = __floats2bfloat162_rn(x, y);
    return *(uint32_t*)&h;
}

// ---------------------------------------------------------------------------
// fp32 -> bf16 hi/lo split conversion
// ---------------------------------------------------------------------------
__global__ __launch_bounds__(256) void conv_kernel(
    const float* __restrict__ src, __nv_bfloat16* __restrict__ hi,
    __nv_bfloat16* __restrict__ lo, int n4)
{
    int i = blockIdx.x * blockDim.x + threadIdx.x;
    if (i >= n4) return;
    float4 v = ((const float4*)src)[i];
    __nv_bfloat16 hx = __float2bfloat16(v.x);
    __nv_bfloat16 hy = __float2bfloat16(v.y);
    __nv_bfloat16 hz = __float2bfloat16(v.z);
    __nv_bfloat16 hw = __float2bfloat16(v.w);
    __nv_bfloat16 lx = __float2bfloat16(v.x - __bfloat162float(hx));
    __nv_bfloat16 ly = __float2bfloat16(v.y - __bfloat162float(hy));
    __nv_bfloat16 lz = __float2bfloat16(v.z - __bfloat162float(hz));
    __nv_bfloat16 lw = __float2bfloat16(v.w - __bfloat162float(hw));
    ((__nv_bfloat162*)hi)[2*i]   = __nv_bfloat162(hx, hy);
    ((__nv_bfloat162*)hi)[2*i+1] = __nv_bfloat162(hz, hw);
    ((__nv_bfloat162*)lo)[2*i]   = __nv_bfloat162(lx, ly);
    ((__nv_bfloat162*)lo)[2*i+1] = __nv_bfloat162(lz, lw);
}

// all four weight matrices in one launch
__global__ __launch_bounds__(256) void conv4_kernel(
    const float* __restrict__ w0, const float* __restrict__ w1,
    const float* __restrict__ w2, const float* __restrict__ w3,
    __nv_bfloat16* __restrict__ hi, __nv_bfloat16* __restrict__ lo)
{
    const int per = HH * HH / 4;                 // float4s per matrix
    int i = blockIdx.x * blockDim.x + threadIdx.x;
    int z = i / per;
    int j = i - z * per;
    const float* src = (z == 0) ? w0 : (z == 1) ? w1 : (z == 2) ? w2 : w3;
    float4 v = ((const float4*)src)[j];
    size_t o = (size_t)z * per + j;
    __nv_bfloat16 hx = __float2bfloat16(v.x);
    __nv_bfloat16 hy = __float2bfloat16(v.y);
    __nv_bfloat16 hz = __float2bfloat16(v.z);
    __nv_bfloat16 hw = __float2bfloat16(v.w);
    ((__nv_bfloat162*)hi)[2*o]   = __nv_bfloat162(hx, hy);
    ((__nv_bfloat162*)hi)[2*o+1] = __nv_bfloat162(hz, hw);
    ((__nv_bfloat162*)lo)[2*o]   = __nv_bfloat162(
        __float2bfloat16(v.x - __bfloat162float(hx)),
        __float2bfloat16(v.y - __bfloat162float(hy)));
    ((__nv_bfloat162*)lo)[2*o+1] = __nv_bfloat162(
        __float2bfloat16(v.z - __bfloat162float(hz)),
        __float2bfloat16(v.w - __bfloat162float(hw)));
}

// ---------------------------------------------------------------------------
// HMMA GEMM v2: CTA tile 256x128, 512 threads (16 warps, 8m x 2n).
// Per K-chunk (64): stage A 64KB (hi/lo) + B 32KB (hi/lo) = 96KB, double buf.
// MODE 0: A = hidden(hi/lo), z selects W/bias -> q/k (split) or vT (split).
// MODE 1: A = ctx(hi/lo), W = Wd -> g_x = gemm + bias + resid (fp32)
// ---------------------------------------------------------------------------
#define STAGE_B 98304
#define GEMM_DSM (2*STAGE_B)

template<int MODE>
__global__ __launch_bounds__(512, 1) void tc_gemm(
    const float* __restrict__ b0, const float* __restrict__ b1,
    const float* __restrict__ b2, const float* __restrict__ resid)
{
    extern __shared__ __align__(1024) char dsm[];

    const int t      = threadIdx.x;
    const int wid    = t >> 5;
    const int l      = t & 31;
    const int warp_m = wid & 7;
    const int warp_n = wid >> 3;
    const int m0     = blockIdx.y * 256;
    const int n0     = blockIdx.x * 128;
    const int z      = (MODE == 0) ? blockIdx.z : 3;

    const __nv_bfloat16* Ahi = (MODE == 0) ? g_ah : g_ch;
    const __nv_bfloat16* Alo = (MODE == 0) ? g_al : g_cl;
    const __nv_bfloat16* Bhi = g_wh + (size_t)z * HH * HH;
    const __nv_bfloat16* Blo = g_wl + (size_t)z * HH * HH;
    const float* bias = (MODE == 1) ? b0 : ((z == 0) ? b0 : (z == 1) ? b1 : b2);

    const uint32_t sbase = (uint32_t)__cvta_generic_to_shared(dsm);

    float acc[2][8][4];
    #pragma unroll
    for (int i = 0; i < 2; i++)
        #pragma unroll
        for (int j = 0; j < 8; j++)
            #pragma unroll
            for (int q = 0; q < 4; q++) acc[i][j][q] = 0.f;

    const int rA = warp_m * 32 + (l & 7) + ((l >> 3) & 1) * 8;
    const int rB = warp_n * 64 + (l & 7) + ((l >> 4) & 1) * 8;
    const int gxA = (l >> 4);
    const int gxB = ((l >> 3) & 1);
    const int lxor = (l & 7);

    // stage chunk c: A 256x64 hi/lo (2x32KB) + B 128x64 hi/lo (2x16KB)
    auto stage = [&](int c, uint32_t bufb) {
        #pragma unroll
        for (int i = 0; i < 12; i++) {
            int idx = i * 512 + t;               // 0..6143
            const void* gp;
            uint32_t dst;
            if (idx < 4096) {                    // A tiles
                int tile = idx >> 11;            // 0 hi, 1 lo
                int w2   = idx & 2047;
                int row  = w2 >> 3;              // 0..255
                int g    = w2 & 7;
                const __nv_bfloat16* src = tile ? Alo : Ahi;
                gp  = src + (size_t)(m0 + row) * HH + c * KC + g * 8;
                dst = bufb + tile * 32768u +
                      (uint32_t)(row * 128 + ((g ^ (row & 7)) * 16));
            } else {                             // B tiles
                int idx2 = idx - 4096;
                int tile = idx2 >> 10;           // 0 hi, 1 lo
                int w2   = idx2 & 1023;
                int row  = w2 >> 3;              // 0..127
                int g    = w2 & 7;
                const __nv_bfloat16* src = tile ? Blo : Bhi;
                gp  = src + (size_t)(n0 + row) * HH + c * KC + g * 8;
                dst = bufb + 65536u + tile * 16384u +
                      (uint32_t)(row * 128 + ((g ^ (row & 7)) * 16));
            }
            cpa16(dst, gp);
        }
    };

    stage(0, sbase);
    CP_COMMIT();

    for (int c = 0; c < NCHUNK; c++) {
        if (c + 1 < NCHUNK) stage(c + 1, sbase + ((c + 1) & 1) * STAGE_B);
        CP_COMMIT();
        CP_WAIT1();
        __syncthreads();

        const uint32_t sb = sbase + (c & 1) * STAGE_B;
        #pragma unroll
        for (int s = 0; s < 4; s++) {
            const int gA = 2 * s + gxA;
            const int gB = 2 * s + gxB;
            uint32_t ah[2][4], al[2][4];
            #pragma unroll
            for (int mt = 0; mt < 2; mt++) {
                int row = rA + mt * 16;
                uint32_t off = (uint32_t)(row * 128 + ((gA ^ lxor) * 16));
                ldm4(ah[mt], sb + off);
                ldm4(al[mt], sb + 32768 + off);
            }
            #pragma unroll
            for (int p = 0; p < 4; p++) {
                int row = rB + p * 16;
                uint32_t off = (uint32_t)(row * 128 + ((gB ^ lxor) * 16));
                uint32_t bh[4], bl[4];
                ldm4(bh, sb + 65536 + off);
                ldm4(bl, sb + 81920 + off);
                #pragma unroll
                for (int mt = 0; mt < 2; mt++) {
                    mma_bf16(acc[mt][2*p],   ah[mt], bh[0], bh[1]);
                    mma_bf16(acc[mt][2*p+1], ah[mt], bh[2], bh[3]);
                    mma_bf16(acc[mt][2*p],   ah[mt], bl[0], bl[1]);
                    mma_bf16(acc[mt][2*p+1], ah[mt], bl[2], bl[3]);
                    mma_bf16(acc[mt][2*p],   al[mt], bh[0], bh[1]);
                    mma_bf16(acc[mt][2*p+1], al[mt], bh[2], bh[3]);
                }
            }
        }
        __syncthreads();
    }

    // ---------------- epilogue ----------------
    const int lr = l >> 2;
    const int lc = (l & 3) * 2;

    float2 bv[8];
    #pragma unroll
    for (int nt = 0; nt < 8; nt++)
        bv[nt] = __ldg((const float2*)(bias + n0 + warp_n * 64 + nt * 8 + lc));

    #pragma unroll
    for (int mt = 0; mt < 2; mt++) {
        #pragma unroll
        for (int half = 0; half < 2; half++) {
            int m = m0 + warp_m * 32 + mt * 16 + lr + half * 8;
            #pragma unroll
            for (int nt = 0; nt < 8; nt++) {
                int n = n0 + warp_n * 64 + nt * 8 + lc;
                float vx = acc[mt][nt][half * 2 + 0] + bv[nt].x;
                float vy = acc[mt][nt][half * 2 + 1] + bv[nt].y;
                if (MODE == 0) {
                    int b_ = m >> 11;
                    int s_ = m & (SS - 1);
                    int head = n >> 6;
                    int d = n & 63;
                    int bh = b_ * NH + head;
                    if (z == 0) { vx *= 0.125f; vy *= 0.125f; }
                    __nv_bfloat16 hx = __float2bfloat16(vx);
                    __nv_bfloat16 hy = __float2bfloat16(vy);
                    __nv_bfloat16 ox = __float2bfloat16(vx - __bfloat162float(hx));
                    __nv_bfloat16 oy = __float2bfloat16(vy - __bfloat162float(hy));
                    if (z == 2) {
                        size_t base = ((size_t)bh * HD + d) * SS + s_;
                        g_vth[base] = hx;       g_vtl[base] = ox;
                        g_vth[base + SS] = hy;  g_vtl[base + SS] = oy;
                    } else {
                        size_t idx = ((size_t)bh * SS + s_) * HD + d;
                        __nv_bfloat16* ph = (z == 0) ? g_qh : g_kh;
                        __nv_bfloat16* pl = (z == 0) ? g_ql : g_kl;
                        *(__nv_bfloat162*)(ph + idx) = __nv_bfloat162(hx, hy);
                        *(__nv_bfloat162*)(pl + idx) = __nv_bfloat162(ox, oy);
                    }
                } else {
                    float2 hv = *(const float2*)(resid + (size_t)m * HH + n);
                    float2 r; r.x = vx + hv.x; r.y = vy + hv.y;
                    *(float2*)(g_x + (size_t)m * HH + n) = r;
                }
            }
        }
    }
}

// ---------------------------------------------------------------------------
// Flash attention on HMMA (bf16-split both GEMMs). Unchanged from R4.
// ---------------------------------------------------------------------------
#define FL_DSM 98304

__global__ __launch_bounds__(256, 1) void flash_tc()
{
    extern __shared__ __align__(1024) char dsm[];
    const int t  = threadIdx.x;
    const int w  = t >> 5;
    const int l  = t & 31;
    const int qt = blockIdx.x;
    const int bh = blockIdx.y;

    const uint32_t sbase = (uint32_t)__cvta_generic_to_shared(dsm);
    const uint32_t qbase = sbase + 65536;

    const size_t kvb = (size_t)bh * SS * HD;
    const size_t vtb = (size_t)bh * HD * SS;

    #pragma unroll
    for (int i = 0; i < 8; i++) {
        int idx  = i * 256 + t;
        int tile = idx >> 10;
        int w2   = idx & 1023;
        int row  = w2 >> 3;
        int g    = w2 & 7;
        const __nv_bfloat16* src = tile ? g_ql : g_qh;
        const void* gp = src + kvb + (size_t)(qt * 128 + row) * HD + g * 8;
        uint32_t off = (uint32_t)(row * 128 + ((g ^ (row & 7)) * 16));
        cpa16(qbase + tile * 16384 + off, gp);
    }
    CP_COMMIT();

    auto stage_kv = [&](int kt, uint32_t bufb) {
        #pragma unroll
        for (int i = 0; i < 8; i++) {
            int idx  = i * 256 + t;
            int tile = idx >> 9;
            int w2   = idx & 511;
            int row  = w2 >> 3;
            int g    = w2 & 7;
            const void* gp;
            if (tile == 0)      gp = g_kh  + kvb + (size_t)(kt * 64 + row) * HD + g * 8;
            else if (tile == 1) gp = g_kl  + kvb + (size_t)(kt * 64 + row) * HD + g * 8;
            else if (tile == 2) gp = g_vth + vtb + (size_t)row * SS + kt * 64 + g * 8;
            else                gp = g_vtl + vtb + (size_t)row * SS + kt * 64 + g * 8;
            uint32_t off = (uint32_t)(row * 128 + ((g ^ (row & 7)) * 16));
            cpa16(bufb + tile * 8192 + off, gp);
        }
    };

    stage_kv(0, sbase);
    CP_COMMIT();
    CP_WAIT1();
    __syncthreads();

    uint32_t qh[4][4], ql[4][4];
    {
        int row = w * 16 + (l & 7) + ((l >> 3) & 1) * 8;
        #pragma unroll
        for (int kk = 0; kk < 4; kk++) {
            uint32_t off = (uint32_t)(row * 128 + (((2 * kk + (l >> 4)) ^ (l & 7)) * 16));
            ldm4(qh[kk], qbase + off);
            ldm4(ql[kk], qbase + 16384 + off);
        }
    }

    const int rB  = (l & 7) + ((l >> 4) & 1) * 8;
    const int gxB = (l >> 3) & 1;
    const int lx  = l & 7;

    float occ[8][4];
    #pragma unroll
    for (int i = 0; i < 8; i++)
        #pragma unroll
        for (int j = 0; j < 4; j++) occ[i][j] = 0.f;
    float mx0 = -1e30f, mx1 = -1e30f, l0 = 0.f, l1 = 0.f;

    for (int kt = 0; kt < SS / 64; kt++) {
        if (kt + 1 < SS / 64) stage_kv(kt + 1, sbase + ((kt + 1) & 1) * 32768);
        CP_COMMIT();
        CP_WAIT1();
        __syncthreads();

        const uint32_t sb = sbase + (kt & 1) * 32768;

        float sc[8][4];
        #pragma unroll
        for (int i = 0; i < 8; i++)
            #pragma unroll
            for (int j = 0; j < 4; j++) sc[i][j] = 0.f;

        #pragma unroll
        for (int pn = 0; pn < 4; pn++) {
            int row = rB + pn * 16;
            #pragma unroll
            for (int s = 0; s < 4; s++) {
                uint32_t off = (uint32_t)(row * 128 + (((2 * s + gxB) ^ lx) * 16));
                uint32_t kh[4], kl[4];
                ldm4(kh, sb + off);
                ldm4(kl, sb + 8192 + off);
                mma_bf16(sc[2*pn],   qh[s], kh[0], kh[1]);
                mma_bf16(sc[2*pn+1], qh[s], kh[2], kh[3]);
                mma_bf16(sc[2*pn],   qh[s], kl[0], kl[1]);
                mma_bf16(sc[2*pn+1], qh[s], kl[2], kl[3]);
                mma_bf16(sc[2*pn],   ql[s], kh[0], kh[1]);
                mma_bf16(sc[2*pn+1], ql[s], kh[2], kh[3]);
            }
        }

        float tm0 = -1e30f, tm1 = -1e30f;
        #pragma unroll
        for (int n = 0; n < 8; n++) {
            tm0 = fmaxf(tm0, fmaxf(sc[n][0], sc[n][1]));
            tm1 = fmaxf(tm1, fmaxf(sc[n][2], sc[n][3]));
        }
        tm0 = fmaxf(tm0, __shfl_xor_sync(0xffffffffu, tm0, 1));
        tm0 = fmaxf(tm0, __shfl_xor_sync(0xffffffffu, tm0, 2));
        tm1 = fmaxf(tm1, __shfl_xor_sync(0xffffffffu, tm1, 1));
        tm1 = fmaxf(tm1, __shfl_xor_sync(0xffffffffu, tm1, 2));

        float mn0 = fmaxf(mx0, tm0);
        float mn1 = fmaxf(mx1, tm1);
        float a0 = __expf(mx0 - mn0);
        float a1 = __expf(mx1 - mn1);
        mx0 = mn0; mx1 = mn1;

        float rs0 = 0.f, rs1 = 0.f;
        #pragma unroll
        for (int n = 0; n < 8; n++) {
            sc[n][0] = __expf(sc[n][0] - mn0); rs0 += sc[n][0];
            sc[n][1] = __expf(sc[n][1] - mn0); rs0 += sc[n][1];
            sc[n][2] = __expf(sc[n][2] - mn1); rs1 += sc[n][2];
            sc[n][3] = __expf(sc[n][3] - mn1); rs1 += sc[n][3];
        }
        rs0 += __shfl_xor_sync(0xffffffffu, rs0, 1);
        rs0 += __shfl_xor_sync(0xffffffffu, rs0, 2);
        rs1 += __shfl_xor_sync(0xffffffffu, rs1, 1);
        rs1 += __shfl_xor_sync(0xffffffffu, rs1, 2);
        l0 = l0 * a0 + rs0;
        l1 = l1 * a1 + rs1;

        #pragma unroll
        for (int nh = 0; nh < 8; nh++) {
            occ[nh][0] *= a0; occ[nh][1] *= a0;
            occ[nh][2] *= a1; occ[nh][3] *= a1;
        }

        uint32_t pah[4][4], pal[4][4];
        #pragma unroll
        for (int tt = 0; tt < 4; tt++) {
            #pragma unroll
            for (int jj = 0; jj < 2; jj++) {
                const float* sp = sc[2 * tt + jj];
                __nv_bfloat16 h0 = __float2bfloat16(sp[0]);
                __nv_bfloat16 h1 = __float2bfloat16(sp[1]);
                __nv_bfloat16 h2 = __float2bfloat16(sp[2]);
                __nv_bfloat16 h3 = __float2bfloat16(sp[3]);
                pah[tt][2*jj]   = packbf(sp[0], sp[1]);
                pah[tt][2*jj+1] = packbf(sp[2], sp[3]);
                pal[tt][2*jj]   = packbf(sp[0] - __bfloat162float(h0),
                                         sp[1] - __bfloat162float(h1));
                pal[tt][2*jj+1] = packbf(sp[2] - __bfloat162float(h2),
                                         sp[3] - __bfloat162float(h3));
            }
        }

        #pragma unroll
        for (int pd = 0; pd < 4; pd++) {
            int row = rB + pd * 16;
            #pragma unroll
            for (int tt = 0; tt < 4; tt++) {
                uint32_t off = (uint32_t)(row * 128 + (((2 * tt + gxB) ^ lx) * 16));
                uint32_t vh[4], vl[4];
                ldm4(vh, sb + 16384 + off);
                ldm4(vl, sb + 24576 + off);
                mma_bf16(occ[2*pd],   pah[tt], vh[0], vh[1]);
                mma_bf16(occ[2*pd+1], pah[tt], vh[2], vh[3]);
                mma_bf16(occ[2*pd],   pal[tt], vh[0], vh[1]);
                mma_bf16(occ[2*pd+1], pal[tt], vh[2], vh[3]);
                mma_bf16(occ[2*pd],   pah[tt], vl[0], vl[1]);
                mma_bf16(occ[2*pd+1], pah[tt], vl[2], vl[3]);
            }
        }
        __syncthreads();
    }

    const float inv0 = 1.f / l0;
    const float inv1 = 1.f / l1;
    const int b_   = bh >> 4;
    const int head = bh & 15;
    const int r    = l >> 2;
    const int c    = 2 * (l & 3);
    const int s0   = qt * 128 + w * 16 + r;
    const int s1   = s0 + 8;

    #pragma unroll
    for (int nh = 0; nh < 8; nh++) {
        int col = head * 64 + nh * 8 + c;
        {
            float v0 = occ[nh][0] * inv0;
            float v1 = occ[nh][1] * inv0;
            __nv_bfloat16 h0 = __float2bfloat16(v0);
            __nv_bfloat16 h1 = __float2bfloat16(v1);
            size_t idx = (size_t)(b_ * SS + s0) * HH + col;
            *(__nv_bfloat162*)(g_ch + idx) = __nv_bfloat162(h0, h1);
            *(__nv_bfloat162*)(g_cl + idx) = __nv_bfloat162(
                __float2bfloat16(v0 - __bfloat162float(h0)),
                __float2bfloat16(v1 - __bfloat162float(h1)));
        }
        {
            float v2 = occ[nh][2] * inv1;
            float v3 = occ[nh][3] * inv1;
            __nv_bfloat16 h2 = __float2bfloat16(v2);
            __nv_bfloat16 h3 = __float2bfloat16(v3);
            size_t idx = (size_t)(b_ * SS + s1) * HH + col;
            *(__nv_bfloat162*)(g_ch + idx) = __nv_bfloat162(h2, h3);
            *(__nv_bfloat162*)(g_cl + idx) = __nv_bfloat162(
                __float2bfloat16(v2 - __bfloat162float(h2)),
                __float2bfloat16(v3 - __bfloat162float(h3)));
        }
    }
}

// ---------------------------------------------------------------------------
// LayerNorm over rows of g_x -> out
// ---------------------------------------------------------------------------
__global__ __launch_bounds__(256) void ln_kernel(
    const float* __restrict__ gamma, const float* __restrict__ beta,
    float* __restrict__ out)
{
    __shared__ float rsum[8];
    __shared__ float rsq[8];

    const int row = blockIdx.x;
    const int t   = threadIdx.x;
    const float* x = g_x + (size_t)row * HH;

    float4 v = ((const float4*)x)[t];
    float sum = v.x + v.y + v.z + v.w;
    float sq  = v.x * v.x + v.y * v.y + v.z * v.z + v.w * v.w;

    #pragma unroll
    for (int off = 16; off > 0; off >>= 1) {
        sum += __shfl_xor_sync(0xffffffffu, sum, off);
        sq  += __shfl_xor_sync(0xffffffffu, sq, off);
    }
    int warp = t >> 5;
    if ((t & 31) == 0) { rsum[warp] = sum; rsq[warp] = sq; }
    __syncthreads();

    float tsum = 0.f, tsq = 0.f;
    #pragma unroll
    for (int w = 0; w < 8; w++) { tsum += rsum[w]; tsq += rsq[w]; }

    const float mu   = tsum * (1.f / HH);
    const float var  = tsq * (1.f / HH) - mu * mu;
    const float rstd = rsqrtf(var + 1e-5f);

    float4 g = ((const float4*)gamma)[t];
    float4 b = ((const float4*)beta)[t];
    float4 r;
    r.x = (v.x - mu) * rstd * g.x + b.x;
    r.y = (v.y - mu) * rstd * g.y + b.y;
    r.z = (v.z - mu) * rstd * g.z + b.z;
    r.w = (v.w - mu) * rstd * g.w + b.w;
    ((float4*)(out + (size_t)row * HH))[t] = r;
}

// ---------------------------------------------------------------------------
extern "C" void kernel_launch(void* const* d_in, const int* in_sizes, int n_in,
                              void* d_out, int out_size)
{
    const float* hs    = (const float*)d_in[0];
    const float* Wq    = (const float*)d_in[1];
    const float* bq    = (const float*)d_in[2];
    const float* Wk    = (const float*)d_in[3];
    const float* bk    = (const float*)d_in[4];
    const float* Wv    = (const float*)d_in[5];
    const float* bv    = (const float*)d_in[6];
    const float* Wd    = (const float*)d_in[7];
    const float* bd    = (const float*)d_in[8];
    const float* gamma = (const float*)d_in[9];
    const float* beta  = (const float*)d_in[10];
    float* out = (float*)d_out;

    cudaFuncSetAttribute(tc_gemm<0>, cudaFuncAttributeMaxDynamicSharedMemorySize, GEMM_DSM);
    cudaFuncSetAttribute(tc_gemm<1>, cudaFuncAttributeMaxDynamicSharedMemorySize, GEMM_DSM);
    cudaFuncSetAttribute(flash_tc,  cudaFuncAttributeMaxDynamicSharedMemorySize, FL_DSM);

    __nv_bfloat16 *p_ah, *p_al, *p_wh, *p_wl;
    cudaGetSymbolAddress((void**)&p_ah, g_ah);
    cudaGetSymbolAddress((void**)&p_al, g_al);
    cudaGetSymbolAddress((void**)&p_wh, g_wh);
    cudaGetSymbolAddress((void**)&p_wl, g_wl);

    // 0) bf16 hi/lo conversions (hidden + 4 weights fused)
    conv_kernel<<<(MTOT*HH/4 + 255)/256, 256>>>(hs, p_ah, p_al, MTOT*HH/4);
    conv4_kernel<<<(4*HH*HH/4 + 255)/256, 256>>>(Wq, Wk, Wv, Wd, p_wh, p_wl);

    // 1) QKV projections (HMMA) -> bf16 split q/k/vT
    dim3 g1(HH / 128, MTOT / 256, 3);
    tc_gemm<0><<<g1, 512, GEMM_DSM>>>(bq, bk, bv, nullptr);

    // 2) Flash attention (HMMA) -> ctx bf16 split
    dim3 g2(SS / 128, BB * NH);
    flash_tc<<<g2, 256, FL_DSM>>>();

    // 3) Output dense + bias + residual (HMMA)
    dim3 g3(HH / 128, MTOT / 256, 1);
    tc_gemm<1><<<g3, 512, GEMM_DSM>>>(bd, nullptr, nullptr, hs);

    // 4) LayerNorm
    ln_kernel<<<MTOT, 256>>>(gamma, beta, out);
}

// round 6
// speedup vs baseline: 3.4874x; 1.0023x over previous
#include <cuda_runtime.h>
#include <cuda_bf16.h>
#include <math.h>
#include <stdint.h>

#define BB 2
#define SS 2048
#define HH 1024
#define NH 16
#define HD 64
#define MTOT (BB*SS)   // 4096
#define KC 64
#define NCHUNK (HH / KC)

// ---------------- scratch (device globals; allocation-free rule) -----------
__device__ float g_x[BB*SS*HH];

__device__ __nv_bfloat16 g_ah[MTOT*HH];     // hidden hi
__device__ __nv_bfloat16 g_al[MTOT*HH];     // hidden lo
__device__ __nv_bfloat16 g_wh[4*HH*HH];     // Wq,Wk,Wv,Wd hi
__device__ __nv_bfloat16 g_wl[4*HH*HH];     // lo
__device__ __nv_bfloat16 g_ch[MTOT*HH];     // ctx hi
__device__ __nv_bfloat16 g_cl[MTOT*HH];     // ctx lo

// attention operands (bf16 hi/lo). q,k: [B*NH][S][HD]; v: transposed [B*NH][HD][S]
__device__ __nv_bfloat16 g_qh[BB*NH*SS*HD];
__device__ __nv_bfloat16 g_ql[BB*NH*SS*HD];
__device__ __nv_bfloat16 g_kh[BB*NH*SS*HD];
__device__ __nv_bfloat16 g_kl[BB*NH*SS*HD];
__device__ __nv_bfloat16 g_vth[BB*NH*HD*SS];
__device__ __nv_bfloat16 g_vtl[BB*NH*HD*SS];

// ---------------- baseline-PTX helpers (sm_80+; OK under compute_103) ------
__device__ __forceinline__ void ldm4(uint32_t* r, uint32_t addr) {
    asm volatile("ldmatrix.sync.aligned.m8n8.x4.shared.b16 {%0,%1,%2,%3}, [%4];"
        : "=r"(r[0]), "=r"(r[1]), "=r"(r[2]), "=r"(r[3]) : "r"(addr));
}

__device__ __forceinline__ void mma_bf16(float* c, const uint32_t* a,
                                         uint32_t b0, uint32_t b1) {
    asm volatile(
        "mma.sync.aligned.m16n8k16.row.col.f32.bf16.bf16.f32 "
        "{%0,%1,%2,%3}, {%4,%5,%6,%7}, {%8,%9}, {%0,%1,%2,%3};"
        : "+f"(c[0]), "+f"(c[1]), "+f"(c[2]), "+f"(c[3])
        : "r"(a[0]), "r"(a[1]), "r"(a[2]), "r"(a[3]), "r"(b0), "r"(b1));
}

__device__ __forceinline__ void cpa16(uint32_t saddr, const void* g) {
    asm volatile("cp.async.cg.shared.global [%0], [%1], 16;"
        :: "r"(saddr), "l"(g) : "memory");
}
#define CP_COMMIT() asm volatile("cp.async.commit_group;" ::: "memory")
#define CP_WAIT1()  asm volatile("cp.async.wait_group 1;" ::: "memory")

__device__ __forceinline__ uint32_t packbf(float x, float y) {
    __nv_bfloat162 h = __floats2bfloat162_rn(x, y);
    return *(uint32_t*)&h;
}

// ---------------------------------------------------------------------------
// fp32 -> bf16 hi/lo split conversion
// ---------------------------------------------------------------------------
__global__ __launch_bounds__(256) void conv_kernel(
    const float* __restrict__ src, __nv_bfloat16* __restrict__ hi,
    __nv_bfloat16* __restrict__ lo, int n4)
{
    int i = blockIdx.x * blockDim.x + threadIdx.x;
    if (i >= n4) return;
    float4 v = ((const float4*)src)[i];
    __nv_bfloat16 hx = __float2bfloat16(v.x);
    __nv_bfloat16 hy = __float2bfloat16(v.y);
    __nv_bfloat16 hz = __float2bfloat16(v.z);
    __nv_bfloat16 hw = __float2bfloat16(v.w);
    __nv_bfloat16 lx = __float2bfloat16(v.x - __bfloat162float(hx));
    __nv_bfloat16 ly = __float2bfloat16(v.y - __bfloat162float(hy));
    __nv_bfloat16 lz = __float2bfloat16(v.z - __bfloat162float(hz));
    __nv_bfloat16 lw = __float2bfloat16(v.w - __bfloat162float(hw));
    ((__nv_bfloat162*)hi)[2*i]   = __nv_bfloat162(hx, hy);
    ((__nv_bfloat162*)hi)[2*i+1] = __nv_bfloat162(hz, hw);
    ((__nv_bfloat162*)lo)[2*i]   = __nv_bfloat162(lx, ly);
    ((__nv_bfloat162*)lo)[2*i+1] = __nv_bfloat162(lz, lw);
}

// all four weight matrices in one launch
__global__ __launch_bounds__(256) void conv4_kernel(
    const float* __restrict__ w0, const float* __restrict__ w1,
    const float* __restrict__ w2, const float* __restrict__ w3,
    __nv_bfloat16* __restrict__ hi, __nv_bfloat16* __restrict__ lo)
{
    const int per = HH * HH / 4;                 // float4s per matrix
    int i = blockIdx.x * blockDim.x + threadIdx.x;
    int z = i / per;
    int j = i - z * per;
    const float* src = (z == 0) ? w0 : (z == 1) ? w1 : (z == 2) ? w2 : w3;
    float4 v = ((const float4*)src)[j];
    size_t o = (size_t)z * per + j;
    __nv_bfloat16 hx = __float2bfloat16(v.x);
    __nv_bfloat16 hy = __float2bfloat16(v.y);
    __nv_bfloat16 hz = __float2bfloat16(v.z);
    __nv_bfloat16 hw = __float2bfloat16(v.w);
    ((__nv_bfloat162*)hi)[2*o]   = __nv_bfloat162(hx, hy);
    ((__nv_bfloat162*)hi)[2*o+1] = __nv_bfloat162(hz, hw);
    ((__nv_bfloat162*)lo)[2*o]   = __nv_bfloat162(
        __float2bfloat16(v.x - __bfloat162float(hx)),
        __float2bfloat16(v.y - __bfloat162float(hy)));
    ((__nv_bfloat162*)lo)[2*o+1] = __nv_bfloat162(
        __float2bfloat16(v.z - __bfloat162float(hz)),
        __float2bfloat16(v.w - __bfloat162float(hw)));
}

// ---------------------------------------------------------------------------
// HMMA GEMM: CTA tile 256x128, 512 threads (16 warps, 8m x 2n).
// Inner MMA blocks issued in 4-accumulator rotation (RAW distance 4).
// ---------------------------------------------------------------------------
#define STAGE_B 98304
#define GEMM_DSM (2*STAGE_B)

template<int MODE>
__global__ __launch_bounds__(512, 1) void tc_gemm(
    const float* __restrict__ b0, const float* __restrict__ b1,
    const float* __restrict__ b2, const float* __restrict__ resid)
{
    extern __shared__ __align__(1024) char dsm[];

    const int t      = threadIdx.x;
    const int wid    = t >> 5;
    const int l      = t & 31;
    const int warp_m = wid & 7;
    const int warp_n = wid >> 3;
    const int m0     = blockIdx.y * 256;
    const int n0     = blockIdx.x * 128;
    const int z      = (MODE == 0) ? blockIdx.z : 3;

    const __nv_bfloat16* Ahi = (MODE == 0) ? g_ah : g_ch;
    const __nv_bfloat16* Alo = (MODE == 0) ? g_al : g_cl;
    const __nv_bfloat16* Bhi = g_wh + (size_t)z * HH * HH;
    const __nv_bfloat16* Blo = g_wl + (size_t)z * HH * HH;
    const float* bias = (MODE == 1) ? b0 : ((z == 0) ? b0 : (z == 1) ? b1 : b2);

    const uint32_t sbase = (uint32_t)__cvta_generic_to_shared(dsm);

    float acc[2][8][4];
    #pragma unroll
    for (int i = 0; i < 2; i++)
        #pragma unroll
        for (int j = 0; j < 8; j++)
            #pragma unroll
            for (int q = 0; q < 4; q++) acc[i][j][q] = 0.f;

    const int rA = warp_m * 32 + (l & 7) + ((l >> 3) & 1) * 8;
    const int rB = warp_n * 64 + (l & 7) + ((l >> 4) & 1) * 8;
    const int gxA = (l >> 4);
    const int gxB = ((l >> 3) & 1);
    const int lxor = (l & 7);

    auto stage = [&](int c, uint32_t bufb) {
        #pragma unroll
        for (int i = 0; i < 12; i++) {
            int idx = i * 512 + t;               // 0..6143
            const void* gp;
            uint32_t dst;
            if (idx < 4096) {                    // A tiles
                int tile = idx >> 11;            // 0 hi, 1 lo
                int w2   = idx & 2047;
                int row  = w2 >> 3;              // 0..255
                int g    = w2 & 7;
                const __nv_bfloat16* src = tile ? Alo : Ahi;
                gp  = src + (size_t)(m0 + row) * HH + c * KC + g * 8;
                dst = bufb + tile * 32768u +
                      (uint32_t)(row * 128 + ((g ^ (row & 7)) * 16));
            } else {                             // B tiles
                int idx2 = idx - 4096;
                int tile = idx2 >> 10;           // 0 hi, 1 lo
                int w2   = idx2 & 1023;
                int row  = w2 >> 3;              // 0..127
                int g    = w2 & 7;
                const __nv_bfloat16* src = tile ? Blo : Bhi;
                gp  = src + (size_t)(n0 + row) * HH + c * KC + g * 8;
                dst = bufb + 65536u + tile * 16384u +
                      (uint32_t)(row * 128 + ((g ^ (row & 7)) * 16));
            }
            cpa16(dst, gp);
        }
    };

    stage(0, sbase);
    CP_COMMIT();

    for (int c = 0; c < NCHUNK; c++) {
        if (c + 1 < NCHUNK) stage(c + 1, sbase + ((c + 1) & 1) * STAGE_B);
        CP_COMMIT();
        CP_WAIT1();
        __syncthreads();

        const uint32_t sb = sbase + (c & 1) * STAGE_B;
        #pragma unroll
        for (int s = 0; s < 4; s++) {
            const int gA = 2 * s + gxA;
            const int gB = 2 * s + gxB;
            uint32_t ah[2][4], al[2][4];
            #pragma unroll
            for (int mt = 0; mt < 2; mt++) {
                int row = rA + mt * 16;
                uint32_t off = (uint32_t)(row * 128 + ((gA ^ lxor) * 16));
                ldm4(ah[mt], sb + off);
                ldm4(al[mt], sb + 32768 + off);
            }
            #pragma unroll
            for (int p = 0; p < 4; p++) {
                int row = rB + p * 16;
                uint32_t off = (uint32_t)(row * 128 + ((gB ^ lxor) * 16));
                uint32_t bh[4], bl[4];
                ldm4(bh, sb + 65536 + off);
                ldm4(bl, sb + 81920 + off);
                float* c0 = acc[0][2*p];
                float* c1 = acc[0][2*p+1];
                float* c2 = acc[1][2*p];
                float* c3 = acc[1][2*p+1];
                // 4-accumulator rotation: RAW distance 4
                mma_bf16(c0, ah[0], bh[0], bh[1]);
                mma_bf16(c1, ah[0], bh[2], bh[3]);
                mma_bf16(c2, ah[1], bh[0], bh[1]);
                mma_bf16(c3, ah[1], bh[2], bh[3]);
                mma_bf16(c0, ah[0], bl[0], bl[1]);
                mma_bf16(c1, ah[0], bl[2], bl[3]);
                mma_bf16(c2, ah[1], bl[0], bl[1]);
                mma_bf16(c3, ah[1], bl[2], bl[3]);
                mma_bf16(c0, al[0], bh[0], bh[1]);
                mma_bf16(c1, al[0], bh[2], bh[3]);
                mma_bf16(c2, al[1], bh[0], bh[1]);
                mma_bf16(c3, al[1], bh[2], bh[3]);
            }
        }
        __syncthreads();
    }

    // ---------------- epilogue ----------------
    const int lr = l >> 2;
    const int lc = (l & 3) * 2;

    float2 bv[8];
    #pragma unroll
    for (int nt = 0; nt < 8; nt++)
        bv[nt] = __ldg((const float2*)(bias + n0 + warp_n * 64 + nt * 8 + lc));

    #pragma unroll
    for (int mt = 0; mt < 2; mt++) {
        #pragma unroll
        for (int half = 0; half < 2; half++) {
            int m = m0 + warp_m * 32 + mt * 16 + lr + half * 8;
            #pragma unroll
            for (int nt = 0; nt < 8; nt++) {
                int n = n0 + warp_n * 64 + nt * 8 + lc;
                float vx = acc[mt][nt][half * 2 + 0] + bv[nt].x;
                float vy = acc[mt][nt][half * 2 + 1] + bv[nt].y;
                if (MODE == 0) {
                    int b_ = m >> 11;
                    int s_ = m & (SS - 1);
                    int head = n >> 6;
                    int d = n & 63;
                    int bh = b_ * NH + head;
                    if (z == 0) { vx *= 0.125f; vy *= 0.125f; }
                    __nv_bfloat16 hx = __float2bfloat16(vx);
                    __nv_bfloat16 hy = __float2bfloat16(vy);
                    __nv_bfloat16 ox = __float2bfloat16(vx - __bfloat162float(hx));
                    __nv_bfloat16 oy = __float2bfloat16(vy - __bfloat162float(hy));
                    if (z == 2) {
                        size_t base = ((size_t)bh * HD + d) * SS + s_;
                        g_vth[base] = hx;       g_vtl[base] = ox;
                        g_vth[base + SS] = hy;  g_vtl[base + SS] = oy;
                    } else {
                        size_t idx = ((size_t)bh * SS + s_) * HD + d;
                        __nv_bfloat16* ph = (z == 0) ? g_qh : g_kh;
                        __nv_bfloat16* pl = (z == 0) ? g_ql : g_kl;
                        *(__nv_bfloat162*)(ph + idx) = __nv_bfloat162(hx, hy);
                        *(__nv_bfloat162*)(pl + idx) = __nv_bfloat162(ox, oy);
                    }
                } else {
                    float2 hv = *(const float2*)(resid + (size_t)m * HH + n);
                    float2 r; r.x = vx + hv.x; r.y = vy + hv.y;
                    *(float2*)(g_x + (size_t)m * HH + n) = r;
                }
            }
        }
    }
}

// ---------------------------------------------------------------------------
// Flash attention on HMMA. MMA blocks in 4-acc rotation (paired 16-row loads).
// ---------------------------------------------------------------------------
#define FL_DSM 98304

__global__ __launch_bounds__(256, 1) void flash_tc()
{
    extern __shared__ __align__(1024) char dsm[];
    const int t  = threadIdx.x;
    const int w  = t >> 5;
    const int l  = t & 31;
    const int qt = blockIdx.x;
    const int bh = blockIdx.y;

    const uint32_t sbase = (uint32_t)__cvta_generic_to_shared(dsm);
    const uint32_t qbase = sbase + 65536;

    const size_t kvb = (size_t)bh * SS * HD;
    const size_t vtb = (size_t)bh * HD * SS;

    #pragma unroll
    for (int i = 0; i < 8; i++) {
        int idx  = i * 256 + t;
        int tile = idx >> 10;
        int w2   = idx & 1023;
        int row  = w2 >> 3;
        int g    = w2 & 7;
        const __nv_bfloat16* src = tile ? g_ql : g_qh;
        const void* gp = src + kvb + (size_t)(qt * 128 + row) * HD + g * 8;
        uint32_t off = (uint32_t)(row * 128 + ((g ^ (row & 7)) * 16));
        cpa16(qbase + tile * 16384 + off, gp);
    }
    CP_COMMIT();

    auto stage_kv = [&](int kt, uint32_t bufb) {
        #pragma unroll
        for (int i = 0; i < 8; i++) {
            int idx  = i * 256 + t;
            int tile = idx >> 9;
            int w2   = idx & 511;
            int row  = w2 >> 3;
            int g    = w2 & 7;
            const void* gp;
            if (tile == 0)      gp = g_kh  + kvb + (size_t)(kt * 64 + row) * HD + g * 8;
            else if (tile == 1) gp = g_kl  + kvb + (size_t)(kt * 64 + row) * HD + g * 8;
            else if (tile == 2) gp = g_vth + vtb + (size_t)row * SS + kt * 64 + g * 8;
            else                gp = g_vtl + vtb + (size_t)row * SS + kt * 64 + g * 8;
            uint32_t off = (uint32_t)(row * 128 + ((g ^ (row & 7)) * 16));
            cpa16(bufb + tile * 8192 + off, gp);
        }
    };

    stage_kv(0, sbase);
    CP_COMMIT();
    CP_WAIT1();
    __syncthreads();

    uint32_t qh[4][4], ql[4][4];
    {
        int row = w * 16 + (l & 7) + ((l >> 3) & 1) * 8;
        #pragma unroll
        for (int kk = 0; kk < 4; kk++) {
            uint32_t off = (uint32_t)(row * 128 + (((2 * kk + (l >> 4)) ^ (l & 7)) * 16));
            ldm4(qh[kk], qbase + off);
            ldm4(ql[kk], qbase + 16384 + off);
        }
    }

    const int rB  = (l & 7) + ((l >> 4) & 1) * 8;
    const int gxB = (l >> 3) & 1;
    const int lx  = l & 7;

    float occ[8][4];
    #pragma unroll
    for (int i = 0; i < 8; i++)
        #pragma unroll
        for (int j = 0; j < 4; j++) occ[i][j] = 0.f;
    float mx0 = -1e30f, mx1 = -1e30f, l0 = 0.f, l1 = 0.f;

    for (int kt = 0; kt < SS / 64; kt++) {
        if (kt + 1 < SS / 64) stage_kv(kt + 1, sbase + ((kt + 1) & 1) * 32768);
        CP_COMMIT();
        CP_WAIT1();
        __syncthreads();

        const uint32_t sb = sbase + (kt & 1) * 32768;

        float sc[8][4];
        #pragma unroll
        for (int i = 0; i < 8; i++)
            #pragma unroll
            for (int j = 0; j < 4; j++) sc[i][j] = 0.f;

        // ---- scores: paired rows, 4-acc rotation ----
        #pragma unroll
        for (int pp = 0; pp < 2; pp++) {
            float* c0 = sc[4*pp+0];
            float* c1 = sc[4*pp+1];
            float* c2 = sc[4*pp+2];
            float* c3 = sc[4*pp+3];
            #pragma unroll
            for (int s = 0; s < 4; s++) {
                uint32_t kh[2][4], kl[2][4];
                #pragma unroll
                for (int j = 0; j < 2; j++) {
                    int row = rB + (2 * pp + j) * 16;
                    uint32_t off = (uint32_t)(row * 128 + (((2 * s + gxB) ^ lx) * 16));
                    ldm4(kh[j], sb + off);
                    ldm4(kl[j], sb + 8192 + off);
                }
                mma_bf16(c0, qh[s], kh[0][0], kh[0][1]);
                mma_bf16(c1, qh[s], kh[0][2], kh[0][3]);
                mma_bf16(c2, qh[s], kh[1][0], kh[1][1]);
                mma_bf16(c3, qh[s], kh[1][2], kh[1][3]);
                mma_bf16(c0, qh[s], kl[0][0], kl[0][1]);
                mma_bf16(c1, qh[s], kl[0][2], kl[0][3]);
                mma_bf16(c2, qh[s], kl[1][0], kl[1][1]);
                mma_bf16(c3, qh[s], kl[1][2], kl[1][3]);
                mma_bf16(c0, ql[s], kh[0][0], kh[0][1]);
                mma_bf16(c1, ql[s], kh[0][2], kh[0][3]);
                mma_bf16(c2, ql[s], kh[1][0], kh[1][1]);
                mma_bf16(c3, ql[s], kh[1][2], kh[1][3]);
            }
        }

        float tm0 = -1e30f, tm1 = -1e30f;
        #pragma unroll
        for (int n = 0; n < 8; n++) {
            tm0 = fmaxf(tm0, fmaxf(sc[n][0], sc[n][1]));
            tm1 = fmaxf(tm1, fmaxf(sc[n][2], sc[n][3]));
        }
        tm0 = fmaxf(tm0, __shfl_xor_sync(0xffffffffu, tm0, 1));
        tm0 = fmaxf(tm0, __shfl_xor_sync(0xffffffffu, tm0, 2));
        tm1 = fmaxf(tm1, __shfl_xor_sync(0xffffffffu, tm1, 1));
        tm1 = fmaxf(tm1, __shfl_xor_sync(0xffffffffu, tm1, 2));

        float mn0 = fmaxf(mx0, tm0);
        float mn1 = fmaxf(mx1, tm1);
        float a0 = __expf(mx0 - mn0);
        float a1 = __expf(mx1 - mn1);
        mx0 = mn0; mx1 = mn1;

        float rs0 = 0.f, rs1 = 0.f;
        #pragma unroll
        for (int n = 0; n < 8; n++) {
            sc[n][0] = __expf(sc[n][0] - mn0); rs0 += sc[n][0];
            sc[n][1] = __expf(sc[n][1] - mn0); rs0 += sc[n][1];
            sc[n][2] = __expf(sc[n][2] - mn1); rs1 += sc[n][2];
            sc[n][3] = __expf(sc[n][3] - mn1); rs1 += sc[n][3];
        }
        rs0 += __shfl_xor_sync(0xffffffffu, rs0, 1);
        rs0 += __shfl_xor_sync(0xffffffffu, rs0, 2);
        rs1 += __shfl_xor_sync(0xffffffffu, rs1, 1);
        rs1 += __shfl_xor_sync(0xffffffffu, rs1, 2);
        l0 = l0 * a0 + rs0;
        l1 = l1 * a1 + rs1;

        #pragma unroll
        for (int nh = 0; nh < 8; nh++) {
            occ[nh][0] *= a0; occ[nh][1] *= a0;
            occ[nh][2] *= a1; occ[nh][3] *= a1;
        }

        uint32_t pah[4][4], pal[4][4];
        #pragma unroll
        for (int tt = 0; tt < 4; tt++) {
            #pragma unroll
            for (int jj = 0; jj < 2; jj++) {
                const float* sp = sc[2 * tt + jj];
                __nv_bfloat16 h0 = __float2bfloat16(sp[0]);
                __nv_bfloat16 h1 = __float2bfloat16(sp[1]);
                __nv_bfloat16 h2 = __float2bfloat16(sp[2]);
                __nv_bfloat16 h3 = __float2bfloat16(sp[3]);
                pah[tt][2*jj]   = packbf(sp[0], sp[1]);
                pah[tt][2*jj+1] = packbf(sp[2], sp[3]);
                pal[tt][2*jj]   = packbf(sp[0] - __bfloat162float(h0),
                                         sp[1] - __bfloat162float(h1));
                pal[tt][2*jj+1] = packbf(sp[2] - __bfloat162float(h2),
                                         sp[3] - __bfloat162float(h3));
            }
        }

        // ---- ctx += P V: paired rows, 4-acc rotation ----
        #pragma unroll
        for (int pp = 0; pp < 2; pp++) {
            float* c0 = occ[4*pp+0];
            float* c1 = occ[4*pp+1];
            float* c2 = occ[4*pp+2];
            float* c3 = occ[4*pp+3];
            #pragma unroll
            for (int tt = 0; tt < 4; tt++) {
                uint32_t vh[2][4], vl[2][4];
                #pragma unroll
                for (int j = 0; j < 2; j++) {
                    int row = rB + (2 * pp + j) * 16;
                    uint32_t off = (uint32_t)(row * 128 + (((2 * tt + gxB) ^ lx) * 16));
                    ldm4(vh[j], sb + 16384 + off);
                    ldm4(vl[j], sb + 24576 + off);
                }
                mma_bf16(c0, pah[tt], vh[0][0], vh[0][1]);
                mma_bf16(c1, pah[tt], vh[0][2], vh[0][3]);
                mma_bf16(c2, pah[tt], vh[1][0], vh[1][1]);
                mma_bf16(c3, pah[tt], vh[1][2], vh[1][3]);
                mma_bf16(c0, pal[tt], vh[0][0], vh[0][1]);
                mma_bf16(c1, pal[tt], vh[0][2], vh[0][3]);
                mma_bf16(c2, pal[tt], vh[1][0], vh[1][1]);
                mma_bf16(c3, pal[tt], vh[1][2], vh[1][3]);
                mma_bf16(c0, pah[tt], vl[0][0], vl[0][1]);
                mma_bf16(c1, pah[tt], vl[0][2], vl[0][3]);
                mma_bf16(c2, pah[tt], vl[1][0], vl[1][1]);
                mma_bf16(c3, pah[tt], vl[1][2], vl[1][3]);
            }
        }
        __syncthreads();
    }

    const float inv0 = 1.f / l0;
    const float inv1 = 1.f / l1;
    const int b_   = bh >> 4;
    const int head = bh & 15;
    const int r    = l >> 2;
    const int c    = 2 * (l & 3);
    const int s0   = qt * 128 + w * 16 + r;
    const int s1   = s0 + 8;

    #pragma unroll
    for (int nh = 0; nh < 8; nh++) {
        int col = head * 64 + nh * 8 + c;
        {
            float v0 = occ[nh][0] * inv0;
            float v1 = occ[nh][1] * inv0;
            __nv_bfloat16 h0 = __float2bfloat16(v0);
            __nv_bfloat16 h1 = __float2bfloat16(v1);
            size_t idx = (size_t)(b_ * SS + s0) * HH + col;
            *(__nv_bfloat162*)(g_ch + idx) = __nv_bfloat162(h0, h1);
            *(__nv_bfloat162*)(g_cl + idx) = __nv_bfloat162(
                __float2bfloat16(v0 - __bfloat162float(h0)),
                __float2bfloat16(v1 - __bfloat162float(h1)));
        }
        {
            float v2 = occ[nh][2] * inv1;
            float v3 = occ[nh][3] * inv1;
            __nv_bfloat16 h2 = __float2bfloat16(v2);
            __nv_bfloat16 h3 = __float2bfloat16(v3);
            size_t idx = (size_t)(b_ * SS + s1) * HH + col;
            *(__nv_bfloat162*)(g_ch + idx) = __nv_bfloat162(h2, h3);
            *(__nv_bfloat162*)(g_cl + idx) = __nv_bfloat162(
                __float2bfloat16(v2 - __bfloat162float(h2)),
                __float2bfloat16(v3 - __bfloat162float(h3)));
        }
    }
}

// ---------------------------------------------------------------------------
// LayerNorm over rows of g_x -> out
// ---------------------------------------------------------------------------
__global__ __launch_bounds__(256) void ln_kernel(
    const float* __restrict__ gamma, const float* __restrict__ beta,
    float* __restrict__ out)
{
    __shared__ float rsum[8];
    __shared__ float rsq[8];

    const int row = blockIdx.x;
    const int t   = threadIdx.x;
    const float* x = g_x + (size_t)row * HH;

    float4 v = ((const float4*)x)[t];
    float sum = v.x + v.y + v.z + v.w;
    float sq  = v.x * v.x + v.y * v.y + v.z * v.z + v.w * v.w;

    #pragma unroll
    for (int off = 16; off > 0; off >>= 1) {
        sum += __shfl_xor_sync(0xffffffffu, sum, off);
        sq  += __shfl_xor_sync(0xffffffffu, sq, off);
    }
    int warp = t >> 5;
    if ((t & 31) == 0) { rsum[warp] = sum; rsq[warp] = sq; }
    __syncthreads();

    float tsum = 0.f, tsq = 0.f;
    #pragma unroll
    for (int w = 0; w < 8; w++) { tsum += rsum[w]; tsq += rsq[w]; }

    const float mu   = tsum * (1.f / HH);
    const float var  = tsq * (1.f / HH) - mu * mu;
    const float rstd = rsqrtf(var + 1e-5f);

    float4 g = ((const float4*)gamma)[t];
    float4 b = ((const float4*)beta)[t];
    float4 r;
    r.x = (v.x - mu) * rstd * g.x + b.x;
    r.y = (v.y - mu) * rstd * g.y + b.y;
    r.z = (v.z - mu) * rstd * g.z + b.z;
    r.w = (v.w - mu) * rstd * g.w + b.w;
    ((float4*)(out + (size_t)row * HH))[t] = r;
}

// ---------------------------------------------------------------------------
extern "C" void kernel_launch(void* const* d_in, const int* in_sizes, int n_in,
                              void* d_out, int out_size)
{
    const float* hs    = (const float*)d_in[0];
    const float* Wq    = (const float*)d_in[1];
    const float* bq    = (const float*)d_in[2];
    const float* Wk    = (const float*)d_in[3];
    const float* bk    = (const float*)d_in[4];
    const float* Wv    = (const float*)d_in[5];
    const float* bv    = (const float*)d_in[6];
    const float* Wd    = (const float*)d_in[7];
    const float* bd    = (const float*)d_in[8];
    const float* gamma = (const float*)d_in[9];
    const float* beta  = (const float*)d_in[10];
    float* out = (float*)d_out;

    cudaFuncSetAttribute(tc_gemm<0>, cudaFuncAttributeMaxDynamicSharedMemorySize, GEMM_DSM);
    cudaFuncSetAttribute(tc_gemm<1>, cudaFuncAttributeMaxDynamicSharedMemorySize, GEMM_DSM);
    cudaFuncSetAttribute(flash_tc,  cudaFuncAttributeMaxDynamicSharedMemorySize, FL_DSM);

    __nv_bfloat16 *p_ah, *p_al, *p_wh, *p_wl;
    cudaGetSymbolAddress((void**)&p_ah, g_ah);
    cudaGetSymbolAddress((void**)&p_al, g_al);
    cudaGetSymbolAddress((void**)&p_wh, g_wh);
    cudaGetSymbolAddress((void**)&p_wl, g_wl);

    // 0) bf16 hi/lo conversions (hidden + 4 weights fused)
    conv_kernel<<<(MTOT*HH/4 + 255)/256, 256>>>(hs, p_ah, p_al, MTOT*HH/4);
    conv4_kernel<<<(4*HH*HH/4 + 255)/256, 256>>>(Wq, Wk, Wv, Wd, p_wh, p_wl);

    // 1) QKV projections (HMMA) -> bf16 split q/k/vT
    dim3 g1(HH / 128, MTOT / 256, 3);
    tc_gemm<0><<<g1, 512, GEMM_DSM>>>(bq, bk, bv, nullptr);

    // 2) Flash attention (HMMA) -> ctx bf16 split
    dim3 g2(SS / 128, BB * NH);
    flash_tc<<<g2, 256, FL_DSM>>>();

    // 3) Output dense + bias + residual (HMMA)
    dim3 g3(HH / 128, MTOT / 256, 1);
    tc_gemm<1><<<g3, 512, GEMM_DSM>>>(bd, nullptr, nullptr, hs);

    // 4) LayerNorm
    ln_kernel<<<MTOT, 256>>>(gamma, beta, out);
}